// round 3
// baseline (speedup 1.0000x reference)
#include <cuda_runtime.h>
#include <cuda_bf16.h>

#define N_NODES 50000
#define N_EDGES 600000
#define IN_CH 128
#define HID_CH 128
#define OUT_CH 64
#define NUM_GRAPHS 512

typedef unsigned long long u64;

// ---------------- device scratch (zero-initialized at load; every call leaves
// g_cnt / g_pool / g_pcnt zeroed again, so replays are identical) ----------------
__device__ float g_t1[N_NODES * HID_CH];       // 25.6 MB
__device__ float g_t2[N_NODES * HID_CH];       // 25.6 MB
__device__ int   g_cnt[N_NODES];
__device__ float g_dinv[N_NODES];
__device__ int   g_rowptr[N_NODES + 1];
__device__ int   g_cursor[N_NODES];
__device__ int   g_csrsrc[N_EDGES];
__device__ float g_pool[NUM_GRAPHS * HID_CH];
__device__ float g_pcnt[NUM_GRAPHS];

__device__ __forceinline__ u64 ffma2(u64 a, u64 b, u64 c) {
    u64 d;
    asm("fma.rn.f32x2 %0, %1, %2, %3;" : "=l"(d) : "l"(a), "l"(b), "l"(c));
    return d;
}

// ---------------- histogram of in-degrees (real edges only) ----------------
__global__ void hist_kernel(const int* __restrict__ dst) {
    int i = blockIdx.x * blockDim.x + threadIdx.x;
    if (i < N_EDGES) atomicAdd(&g_cnt[dst[i]], 1);
}

// ---------------- single-block scan -> rowptr, cursor, dinv; re-zeroes g_cnt ----------------
__global__ void scan_kernel() {
    __shared__ int part[1024];
    const int tid = threadIdx.x;
    const int chunk = (N_NODES + 1023) / 1024;   // 49
    int start = tid * chunk;
    int end = start + chunk; if (end > N_NODES) end = N_NODES;
    int s = 0;
    for (int i = start; i < end; i++) s += g_cnt[i];
    part[tid] = s;
    __syncthreads();
    for (int off = 1; off < 1024; off <<= 1) {
        int v = 0;
        if (tid >= off) v = part[tid - off];
        __syncthreads();
        part[tid] += v;
        __syncthreads();
    }
    int run = (tid == 0) ? 0 : part[tid - 1];
    for (int i = start; i < end; i++) {
        int c = g_cnt[i];
        g_cnt[i] = 0;                           // ready for next call
        g_rowptr[i] = run;
        g_cursor[i] = run;
        g_dinv[i] = rsqrtf((float)(c + 1));     // +1 self-loop
        run += c;
    }
    if (tid == 1023) g_rowptr[N_NODES] = part[1023];
}

// ---------------- fill CSR (src indices grouped by dst) ----------------
__global__ void fill_kernel(const int* __restrict__ src,
                            const int* __restrict__ dst) {
    int i = blockIdx.x * blockDim.x + threadIdx.x;
    if (i < N_EDGES) {
        int d = dst[i];
        int pos = atomicAdd(&g_cursor[d], 1);
        g_csrsrc[pos] = src[i];
    }
}

// ---------------- GEMM: C[row] = (A[row] @ W) * dinv[row], f32x2 packed ----------------
// 128x128 tile per block, 256 threads, 8x8 micro-tile, FFMA2 inner loop.
// smem: W [128x128] = 64KB, xs2 (A chunk transposed + splatted) 32x256 = 32KB.
__global__ __launch_bounds__(256, 2) void gemm128(const float* __restrict__ A,
                                                  const float* __restrict__ W,
                                                  const float* __restrict__ dinv,
                                                  float* __restrict__ C, int M) {
    extern __shared__ float sm[];
    float* wsf = sm;                 // 16384 floats
    float* xs2 = sm + 16384;         // 8192 floats: xs2[k][2r]=xs2[k][2r+1]=A[row0+r][kc+k]
    const int tid = threadIdx.x;

    for (int i = tid; i < 4096; i += 256)
        ((float4*)wsf)[i] = ((const float4*)W)[i];

    const int row0 = blockIdx.x * 128;
    const int tx = tid & 15, ty = tid >> 4;
    const int r0 = ty * 8, c0 = tx * 8;

    u64 acc[8][4];
#pragma unroll
    for (int i = 0; i < 8; i++)
#pragma unroll
        for (int j = 0; j < 4; j++) acc[i][j] = 0ULL;

    for (int kc = 0; kc < 128; kc += 32) {
        __syncthreads();
        for (int i = tid; i < 1024; i += 256) {
            int r = i >> 3, k4 = i & 7;
            int row = row0 + r;
            float4 v = make_float4(0.f, 0.f, 0.f, 0.f);
            if (row < M) v = *(const float4*)&A[row * 128 + kc + k4 * 4];
            int kb = k4 * 4;
            *(float2*)&xs2[(kb + 0) * 256 + 2 * r] = make_float2(v.x, v.x);
            *(float2*)&xs2[(kb + 1) * 256 + 2 * r] = make_float2(v.y, v.y);
            *(float2*)&xs2[(kb + 2) * 256 + 2 * r] = make_float2(v.z, v.z);
            *(float2*)&xs2[(kb + 3) * 256 + 2 * r] = make_float2(v.w, v.w);
        }
        __syncthreads();
#pragma unroll
        for (int kk = 0; kk < 32; kk++) {
            const ulonglong2* ar = (const ulonglong2*)&xs2[kk * 256 + 2 * r0];
            ulonglong2 a01 = ar[0], a23 = ar[1], a45 = ar[2], a67 = ar[3];
            const ulonglong2* br = (const ulonglong2*)&wsf[(kc + kk) * 128 + c0];
            ulonglong2 b03 = br[0], b47 = br[1];
            u64 ap[8] = {a01.x, a01.y, a23.x, a23.y, a45.x, a45.y, a67.x, a67.y};
            u64 bp[4] = {b03.x, b03.y, b47.x, b47.y};
#pragma unroll
            for (int i = 0; i < 8; i++)
#pragma unroll
                for (int j = 0; j < 4; j++)
                    acc[i][j] = ffma2(ap[i], bp[j], acc[i][j]);
        }
    }

#pragma unroll
    for (int i = 0; i < 8; i++) {
        int row = row0 + r0 + i;
        if (row < M) {
            float dv = dinv[row];
            float o[8];
#pragma unroll
            for (int j = 0; j < 4; j++) {
                float lo, hi;
                asm("mov.b64 {%0, %1}, %2;" : "=f"(lo), "=f"(hi) : "l"(acc[i][j]));
                o[2 * j] = lo * dv;
                o[2 * j + 1] = hi * dv;
            }
            *(float4*)&C[row * 128 + c0]     = make_float4(o[0], o[1], o[2], o[3]);
            *(float4*)&C[row * 128 + c0 + 4] = make_float4(o[4], o[5], o[6], o[7]);
        }
    }
}
#define GEMM_SMEM ((16384 + 8192) * 4)

// ---------------- aggregation on pre-scaled features h' = (xW)*dinv ----------------
// out[d] = relu(dinv[d] * (sum_{s in N(d)} h'[s] + h'[d]) + b)
__global__ void agg_kernel(const float* __restrict__ hin,
                           float* __restrict__ hout,
                           const float* __restrict__ bias) {
    int gid = blockIdx.x * blockDim.x + threadIdx.x;
    int node = gid >> 5;
    int lane = gid & 31;
    if (node >= N_NODES) return;

    const float dv = g_dinv[node];
    const float4* h4 = (const float4*)hin;

    float4 acc = __ldg(&h4[node * 32 + lane]);   // self-loop (pre-scaled)

    int e0 = g_rowptr[node];
    int e1 = g_rowptr[node + 1];
    int e = e0;
    for (; e + 4 <= e1; e += 4) {
        int s0 = g_csrsrc[e], s1 = g_csrsrc[e + 1], s2 = g_csrsrc[e + 2], s3 = g_csrsrc[e + 3];
        float4 v0 = __ldg(&h4[s0 * 32 + lane]);
        float4 v1 = __ldg(&h4[s1 * 32 + lane]);
        float4 v2 = __ldg(&h4[s2 * 32 + lane]);
        float4 v3 = __ldg(&h4[s3 * 32 + lane]);
        acc.x += v0.x + v1.x + v2.x + v3.x;
        acc.y += v0.y + v1.y + v2.y + v3.y;
        acc.z += v0.z + v1.z + v2.z + v3.z;
        acc.w += v0.w + v1.w + v2.w + v3.w;
    }
    for (; e < e1; e++) {
        int s = g_csrsrc[e];
        float4 v = __ldg(&h4[s * 32 + lane]);
        acc.x += v.x; acc.y += v.y; acc.z += v.z; acc.w += v.w;
    }

    float4 b = ((const float4*)bias)[lane];
    acc.x = fmaxf(acc.x * dv + b.x, 0.0f);
    acc.y = fmaxf(acc.y * dv + b.y, 0.0f);
    acc.z = fmaxf(acc.z * dv + b.z, 0.0f);
    acc.w = fmaxf(acc.w * dv + b.w, 0.0f);
    ((float4*)hout)[node * 32 + lane] = acc;
}

// ---------------- layer-2 aggregation fused with mean-pool accumulation ----------------
__global__ void agg_pool_kernel(const float* __restrict__ hin,
                                const float* __restrict__ bias,
                                const int* __restrict__ batch) {
    int gid = blockIdx.x * blockDim.x + threadIdx.x;
    int node = gid >> 5;
    int lane = gid & 31;
    if (node >= N_NODES) return;

    const float dv = g_dinv[node];
    const float4* h4 = (const float4*)hin;

    float4 acc = __ldg(&h4[node * 32 + lane]);

    int e0 = g_rowptr[node];
    int e1 = g_rowptr[node + 1];
    int e = e0;
    for (; e + 4 <= e1; e += 4) {
        int s0 = g_csrsrc[e], s1 = g_csrsrc[e + 1], s2 = g_csrsrc[e + 2], s3 = g_csrsrc[e + 3];
        float4 v0 = __ldg(&h4[s0 * 32 + lane]);
        float4 v1 = __ldg(&h4[s1 * 32 + lane]);
        float4 v2 = __ldg(&h4[s2 * 32 + lane]);
        float4 v3 = __ldg(&h4[s3 * 32 + lane]);
        acc.x += v0.x + v1.x + v2.x + v3.x;
        acc.y += v0.y + v1.y + v2.y + v3.y;
        acc.z += v0.z + v1.z + v2.z + v3.z;
        acc.w += v0.w + v1.w + v2.w + v3.w;
    }
    for (; e < e1; e++) {
        int s = g_csrsrc[e];
        float4 v = __ldg(&h4[s * 32 + lane]);
        acc.x += v.x; acc.y += v.y; acc.z += v.z; acc.w += v.w;
    }

    float4 b = ((const float4*)bias)[lane];
    int g = batch[node];
    float* p = &g_pool[g * 128 + lane * 4];
    atomicAdd(p + 0, fmaxf(acc.x * dv + b.x, 0.0f));
    atomicAdd(p + 1, fmaxf(acc.y * dv + b.y, 0.0f));
    atomicAdd(p + 2, fmaxf(acc.z * dv + b.z, 0.0f));
    atomicAdd(p + 3, fmaxf(acc.w * dv + b.w, 0.0f));
    if (lane == 0) atomicAdd(&g_pcnt[g], 1.0f);
}

// ---------------- final: out[512,64] = (pool/cnt) @ Wlin + blin; re-zero pool ----------------
__global__ void final_kernel(const float* __restrict__ Wlin,
                             const float* __restrict__ blin,
                             float* __restrict__ out) {
    __shared__ float ws[HID_CH * OUT_CH];
    __shared__ float bs[OUT_CH];
    for (int i = threadIdx.x; i < HID_CH * OUT_CH; i += 256) ws[i] = Wlin[i];
    if (threadIdx.x < OUT_CH) bs[threadIdx.x] = blin[threadIdx.x];
    __syncthreads();

    int t = blockIdx.x * 256 + threadIdx.x;    // 0..32767; block owns graphs [b*4, b*4+4)
    int g = t >> 6, o = t & 63;
    float inv = 1.0f / fmaxf(g_pcnt[g], 1.0f);
    float s = 0.0f;
#pragma unroll 8
    for (int k = 0; k < 128; k++)
        s += g_pool[g * 128 + k] * ws[k * 64 + o];
    out[t] = s * inv + bs[o];

    __syncthreads();   // all reads of this block's g_pool graphs done
    int base = blockIdx.x * 512;               // 4 graphs * 128 ch
    g_pool[base + threadIdx.x] = 0.0f;
    g_pool[base + 256 + threadIdx.x] = 0.0f;
    if (threadIdx.x < 4) g_pcnt[blockIdx.x * 4 + threadIdx.x] = 0.0f;
}

// ---------------- launch ----------------
extern "C" void kernel_launch(void* const* d_in, const int* in_sizes, int n_in,
                              void* d_out, int out_size) {
    const float* x    = (const float*)d_in[0];
    const float* W1   = (const float*)d_in[1];
    const float* b1   = (const float*)d_in[2];
    const float* W2   = (const float*)d_in[3];
    const float* b2   = (const float*)d_in[4];
    const float* Wlin = (const float*)d_in[5];
    const float* blin = (const float*)d_in[6];
    const int* edge   = (const int*)d_in[7];     // JAX x64-disabled: int64 -> int32
    const int* batch  = (const int*)d_in[8];
    float* out = (float*)d_out;

    const int* src = edge;
    const int* dst = edge + N_EDGES;

    float *t1, *t2, *dinv;
    cudaGetSymbolAddress((void**)&t1, g_t1);
    cudaGetSymbolAddress((void**)&t2, g_t2);
    cudaGetSymbolAddress((void**)&dinv, g_dinv);

    cudaFuncSetAttribute(gemm128, cudaFuncAttributeMaxDynamicSharedMemorySize, GEMM_SMEM);

    const int eb = (N_EDGES + 255) / 256;               // 2344
    const int gb = (N_NODES + 127) / 128;               // 391
    const int ab = (N_NODES * 32) / 256;                // 6250

    hist_kernel<<<eb, 256>>>(dst);
    scan_kernel<<<1, 1024>>>();
    fill_kernel<<<eb, 256>>>(src, dst);

    gemm128<<<gb, 256, GEMM_SMEM>>>(x, W1, dinv, t1, N_NODES);
    agg_kernel<<<ab, 256>>>(t1, t2, b1);

    gemm128<<<gb, 256, GEMM_SMEM>>>(t2, W2, dinv, t1, N_NODES);
    agg_pool_kernel<<<ab, 256>>>(t1, b2, batch);

    final_kernel<<<128, 256>>>(Wlin, blin, out);
}

// round 5
// speedup vs baseline: 1.0179x; 1.0179x over previous
#include <cuda_runtime.h>
#include <cuda_bf16.h>
#include <mma.h>
#include <cstdint>

using namespace nvcuda;

#define N_NODES 50000
#define N_EDGES 600000
#define IN_CH 128
#define HID_CH 128
#define OUT_CH 64
#define NUM_GRAPHS 512

// ---------------- device scratch (zero-initialized at load; every call leaves
// g_cnt / g_pool / g_pcnt zeroed again, so replays are identical) ----------------
__device__ float g_t1[N_NODES * HID_CH];       // 25.6 MB
__device__ float g_t2[N_NODES * HID_CH];       // 25.6 MB
__device__ int   g_cnt[N_NODES];
__device__ float g_dinv[N_NODES];
__device__ int   g_rowptr[N_NODES + 1];
__device__ int   g_cursor[N_NODES];
__device__ int   g_csrsrc[N_EDGES];
__device__ float g_pool[NUM_GRAPHS * HID_CH];
__device__ float g_pcnt[NUM_GRAPHS];

__device__ __forceinline__ void split_bf16(float x, unsigned short& h, unsigned short& l) {
    __nv_bfloat16 hb = __float2bfloat16_rn(x);
    float r = x - __bfloat162float(hb);
    __nv_bfloat16 lb = __float2bfloat16_rn(r);
    h = __bfloat16_as_ushort(hb);
    l = __bfloat16_as_ushort(lb);
}

// ---------------- histogram of in-degrees (real edges only) ----------------
__global__ void hist_kernel(const int* __restrict__ dst) {
    int i = blockIdx.x * blockDim.x + threadIdx.x;
    if (i < N_EDGES) atomicAdd(&g_cnt[dst[i]], 1);
}

// ---------------- single-block scan -> rowptr, cursor, dinv; re-zeroes g_cnt ----------------
__global__ void scan_kernel() {
    __shared__ int part[1024];
    const int tid = threadIdx.x;
    const int chunk = (N_NODES + 1023) / 1024;   // 49
    int start = tid * chunk;
    int end = start + chunk; if (end > N_NODES) end = N_NODES;
    int s = 0;
    for (int i = start; i < end; i++) s += g_cnt[i];
    part[tid] = s;
    __syncthreads();
    for (int off = 1; off < 1024; off <<= 1) {
        int v = 0;
        if (tid >= off) v = part[tid - off];
        __syncthreads();
        part[tid] += v;
        __syncthreads();
    }
    int run = (tid == 0) ? 0 : part[tid - 1];
    for (int i = start; i < end; i++) {
        int c = g_cnt[i];
        g_cnt[i] = 0;                           // ready for next call
        g_rowptr[i] = run;
        g_cursor[i] = run;
        g_dinv[i] = rsqrtf((float)(c + 1));     // +1 self-loop
        run += c;
    }
    if (tid == 1023) g_rowptr[N_NODES] = part[1023];
}

// ---------------- fill CSR (src indices grouped by dst) ----------------
__global__ void fill_kernel(const int* __restrict__ src,
                            const int* __restrict__ dst) {
    int i = blockIdx.x * blockDim.x + threadIdx.x;
    if (i < N_EDGES) {
        int d = dst[i];
        int pos = atomicAdd(&g_cursor[d], 1);
        g_csrsrc[pos] = src[i];
    }
}

// ============ tensor-core GEMM via wmma: C[row] = (A[row] @ W) * dinv[row] ============
// 128x128 tile per CTA, 256 threads (8 warps, 4x2 warp grid of 32x64 warp tiles).
// bf16 hi/lo split, 3 passes (Ah*Bh + Ah*Bl + Al*Bh), fp32 accumulators.
#define KP 136                                  // padded K stride in bf16 elements
#define TILE_BYTES (128 * KP * 2)               // 34816 B per tile
#define SMEM_TC (4 * TILE_BYTES)                // Ah, Al, Bh, Bl = 139264 B

__global__ __launch_bounds__(256, 1)
void gemm_tc(const float* __restrict__ A, const float* __restrict__ W,
             const float* __restrict__ dinv, float* __restrict__ C, int M) {
    extern __shared__ char smc[];
    __nv_bfloat16* Ah = (__nv_bfloat16*)smc;
    __nv_bfloat16* Al = Ah + 128 * KP;
    __nv_bfloat16* Bh = Al + 128 * KP;
    __nv_bfloat16* Bl = Bh + 128 * KP;

    const int tid = threadIdx.x;
    const int row0 = blockIdx.x * 128;

    // ---- stage A (hi/lo split), [r][k] row-major, padded ----
    const float4* A4 = (const float4*)A;
    for (int idx = tid; idx < 128 * 32; idx += 256) {
        int r = idx >> 5;
        int kq = idx & 31;                       // float4 index along k
        int row = row0 + r;
        float4 v = make_float4(0.f, 0.f, 0.f, 0.f);
        if (row < M) v = A4[row * 32 + kq];
        unsigned short h0, h1, h2, h3, l0, l1, l2, l3;
        split_bf16(v.x, h0, l0); split_bf16(v.y, h1, l1);
        split_bf16(v.z, h2, l2); split_bf16(v.w, h3, l3);
        int e = r * KP + kq * 4;                 // element offset, 8B-aligned (*2)
        *(uint2*)&Ah[e] = make_uint2((uint32_t)h0 | ((uint32_t)h1 << 16),
                                     (uint32_t)h2 | ((uint32_t)h3 << 16));
        *(uint2*)&Al[e] = make_uint2((uint32_t)l0 | ((uint32_t)l1 << 16),
                                     (uint32_t)l2 | ((uint32_t)l3 << 16));
    }

    // ---- stage B = W^T (hi/lo split): element (k,n) at B[n*KP + k] (col_major K x N) ----
    for (int idx = tid; idx < 16384; idx += 256) {
        int k = idx >> 7, n = idx & 127;
        float w = W[idx];                        // W[k][n], coalesced read
        unsigned short h, l;
        split_bf16(w, h, l);
        Bh[n * KP + k] = __ushort_as_bfloat16(h);
        Bl[n * KP + k] = __ushort_as_bfloat16(l);
    }
    __syncthreads();

    // ---- wmma main loops ----
    const int wid = tid >> 5;
    const int wm = wid & 3;                      // 4 warps along M (32 rows each)
    const int wn = wid >> 2;                     // 2 warps along N (64 cols each)

    wmma::fragment<wmma::accumulator, 16, 16, 16, float> cf[2][4];
#pragma unroll
    for (int i = 0; i < 2; i++)
#pragma unroll
        for (int j = 0; j < 4; j++) wmma::fill_fragment(cf[i][j], 0.0f);

    const __nv_bfloat16* APASS[3] = {Ah, Ah, Al};
    const __nv_bfloat16* BPASS[3] = {Bh, Bl, Bh};

#pragma unroll
    for (int p = 0; p < 3; p++) {
        const __nv_bfloat16* Ap = APASS[p];
        const __nv_bfloat16* Bp = BPASS[p];
#pragma unroll
        for (int k8 = 0; k8 < 8; k8++) {
            wmma::fragment<wmma::matrix_a, 16, 16, 16, __nv_bfloat16, wmma::row_major> a0, a1;
            wmma::load_matrix_sync(a0, Ap + (wm * 32 + 0)  * KP + k8 * 16, KP);
            wmma::load_matrix_sync(a1, Ap + (wm * 32 + 16) * KP + k8 * 16, KP);
#pragma unroll
            for (int j = 0; j < 4; j++) {
                wmma::fragment<wmma::matrix_b, 16, 16, 16, __nv_bfloat16, wmma::col_major> b;
                wmma::load_matrix_sync(b, Bp + (wn * 64 + j * 16) * KP + k8 * 16, KP);
                wmma::mma_sync(cf[0][j], a0, b, cf[0][j]);
                wmma::mma_sync(cf[1][j], a1, b, cf[1][j]);
            }
        }
    }

    __syncthreads();                             // all warps done reading A/B smem
    float* cs = (float*)smc;                     // reuse smem: 128x128 f32 = 64KB
#pragma unroll
    for (int i = 0; i < 2; i++)
#pragma unroll
        for (int j = 0; j < 4; j++)
            wmma::store_matrix_sync(&cs[(wm * 32 + i * 16) * 128 + wn * 64 + j * 16],
                                    cf[i][j], 128, wmma::mem_row_major);
    __syncthreads();

    // ---- epilogue: scale by dinv[row], write out ----
    float4* C4 = (float4*)C;
    const float4* cs4 = (const float4*)cs;
    for (int idx = tid; idx < 128 * 32; idx += 256) {
        int r = idx >> 5, cq = idx & 31;
        int row = row0 + r;
        if (row < M) {
            float dv = dinv[row];
            float4 v = cs4[r * 32 + cq];
            v.x *= dv; v.y *= dv; v.z *= dv; v.w *= dv;
            C4[row * 32 + cq] = v;
        }
    }
}

// ---------------- aggregation on pre-scaled features h' = (xW)*dinv ----------------
// out[d] = relu(dinv[d] * (sum_{s in N(d)} h'[s] + h'[d]) + b)
__global__ void agg_kernel(const float* __restrict__ hin,
                           float* __restrict__ hout,
                           const float* __restrict__ bias) {
    int gid = blockIdx.x * blockDim.x + threadIdx.x;
    int node = gid >> 5;
    int lane = gid & 31;
    if (node >= N_NODES) return;

    const float dv = g_dinv[node];
    const float4* h4 = (const float4*)hin;

    float4 acc = __ldg(&h4[node * 32 + lane]);   // self-loop (pre-scaled)

    int e0 = g_rowptr[node];
    int e1 = g_rowptr[node + 1];
    int e = e0;
    for (; e + 4 <= e1; e += 4) {
        int s0 = g_csrsrc[e], s1 = g_csrsrc[e + 1], s2 = g_csrsrc[e + 2], s3 = g_csrsrc[e + 3];
        float4 v0 = __ldg(&h4[s0 * 32 + lane]);
        float4 v1 = __ldg(&h4[s1 * 32 + lane]);
        float4 v2 = __ldg(&h4[s2 * 32 + lane]);
        float4 v3 = __ldg(&h4[s3 * 32 + lane]);
        acc.x += v0.x + v1.x + v2.x + v3.x;
        acc.y += v0.y + v1.y + v2.y + v3.y;
        acc.z += v0.z + v1.z + v2.z + v3.z;
        acc.w += v0.w + v1.w + v2.w + v3.w;
    }
    for (; e < e1; e++) {
        int s = g_csrsrc[e];
        float4 v = __ldg(&h4[s * 32 + lane]);
        acc.x += v.x; acc.y += v.y; acc.z += v.z; acc.w += v.w;
    }

    float4 b = ((const float4*)bias)[lane];
    acc.x = fmaxf(acc.x * dv + b.x, 0.0f);
    acc.y = fmaxf(acc.y * dv + b.y, 0.0f);
    acc.z = fmaxf(acc.z * dv + b.z, 0.0f);
    acc.w = fmaxf(acc.w * dv + b.w, 0.0f);
    ((float4*)hout)[node * 32 + lane] = acc;
}

// ---------------- layer-2 aggregation fused with mean-pool accumulation ----------------
__global__ void agg_pool_kernel(const float* __restrict__ hin,
                                const float* __restrict__ bias,
                                const int* __restrict__ batch) {
    int gid = blockIdx.x * blockDim.x + threadIdx.x;
    int node = gid >> 5;
    int lane = gid & 31;
    if (node >= N_NODES) return;

    const float dv = g_dinv[node];
    const float4* h4 = (const float4*)hin;

    float4 acc = __ldg(&h4[node * 32 + lane]);

    int e0 = g_rowptr[node];
    int e1 = g_rowptr[node + 1];
    int e = e0;
    for (; e + 4 <= e1; e += 4) {
        int s0 = g_csrsrc[e], s1 = g_csrsrc[e + 1], s2 = g_csrsrc[e + 2], s3 = g_csrsrc[e + 3];
        float4 v0 = __ldg(&h4[s0 * 32 + lane]);
        float4 v1 = __ldg(&h4[s1 * 32 + lane]);
        float4 v2 = __ldg(&h4[s2 * 32 + lane]);
        float4 v3 = __ldg(&h4[s3 * 32 + lane]);
        acc.x += v0.x + v1.x + v2.x + v3.x;
        acc.y += v0.y + v1.y + v2.y + v3.y;
        acc.z += v0.z + v1.z + v2.z + v3.z;
        acc.w += v0.w + v1.w + v2.w + v3.w;
    }
    for (; e < e1; e++) {
        int s = g_csrsrc[e];
        float4 v = __ldg(&h4[s * 32 + lane]);
        acc.x += v.x; acc.y += v.y; acc.z += v.z; acc.w += v.w;
    }

    float4 b = ((const float4*)bias)[lane];
    int g = batch[node];
    float* p = &g_pool[g * 128 + lane * 4];
    atomicAdd(p + 0, fmaxf(acc.x * dv + b.x, 0.0f));
    atomicAdd(p + 1, fmaxf(acc.y * dv + b.y, 0.0f));
    atomicAdd(p + 2, fmaxf(acc.z * dv + b.z, 0.0f));
    atomicAdd(p + 3, fmaxf(acc.w * dv + b.w, 0.0f));
    if (lane == 0) atomicAdd(&g_pcnt[g], 1.0f);
}

// ---------------- final: out[512,64] = (pool/cnt) @ Wlin + blin; re-zero pool ----------------
__global__ void final_kernel(const float* __restrict__ Wlin,
                             const float* __restrict__ blin,
                             float* __restrict__ out) {
    __shared__ float ws[HID_CH * OUT_CH];
    __shared__ float bs[OUT_CH];
    for (int i = threadIdx.x; i < HID_CH * OUT_CH; i += 256) ws[i] = Wlin[i];
    if (threadIdx.x < OUT_CH) bs[threadIdx.x] = blin[threadIdx.x];
    __syncthreads();

    int t = blockIdx.x * 256 + threadIdx.x;    // block owns graphs [b*4, b*4+4)
    int g = t >> 6, o = t & 63;
    float inv = 1.0f / fmaxf(g_pcnt[g], 1.0f);
    float s = 0.0f;
#pragma unroll 8
    for (int k = 0; k < 128; k++)
        s += g_pool[g * 128 + k] * ws[k * 64 + o];
    out[t] = s * inv + bs[o];

    __syncthreads();   // all reads of this block's g_pool graphs done
    int base = blockIdx.x * 512;               // 4 graphs * 128 ch
    g_pool[base + threadIdx.x] = 0.0f;
    g_pool[base + 256 + threadIdx.x] = 0.0f;
    if (threadIdx.x < 4) g_pcnt[blockIdx.x * 4 + threadIdx.x] = 0.0f;
}

// ---------------- launch ----------------
extern "C" void kernel_launch(void* const* d_in, const int* in_sizes, int n_in,
                              void* d_out, int out_size) {
    const float* x    = (const float*)d_in[0];
    const float* W1   = (const float*)d_in[1];
    const float* b1   = (const float*)d_in[2];
    const float* W2   = (const float*)d_in[3];
    const float* b2   = (const float*)d_in[4];
    const float* Wlin = (const float*)d_in[5];
    const float* blin = (const float*)d_in[6];
    const int* edge   = (const int*)d_in[7];     // JAX x64-disabled: int64 -> int32
    const int* batch  = (const int*)d_in[8];
    float* out = (float*)d_out;

    const int* src = edge;
    const int* dst = edge + N_EDGES;

    float *t1, *t2, *dinv;
    cudaGetSymbolAddress((void**)&t1, g_t1);
    cudaGetSymbolAddress((void**)&t2, g_t2);
    cudaGetSymbolAddress((void**)&dinv, g_dinv);

    cudaFuncSetAttribute(gemm_tc, cudaFuncAttributeMaxDynamicSharedMemorySize, SMEM_TC);

    const int eb = (N_EDGES + 255) / 256;               // 2344
    const int gb = (N_NODES + 127) / 128;               // 391
    const int ab = (N_NODES * 32) / 256;                // 6250

    hist_kernel<<<eb, 256>>>(dst);
    scan_kernel<<<1, 1024>>>();
    fill_kernel<<<eb, 256>>>(src, dst);

    gemm_tc<<<gb, 256, SMEM_TC>>>(x, W1, dinv, t1, N_NODES);
    agg_kernel<<<ab, 256>>>(t1, t2, b1);

    gemm_tc<<<gb, 256, SMEM_TC>>>(t2, W2, dinv, t1, N_NODES);
    agg_pool_kernel<<<ab, 256>>>(t1, b2, batch);

    final_kernel<<<128, 256>>>(Wlin, blin, out);
}

// round 6
// speedup vs baseline: 1.0848x; 1.0657x over previous
#include <cuda_runtime.h>
#include <cuda_bf16.h>
#include <mma.h>
#include <cstdint>

using namespace nvcuda;

#define N_NODES 50000
#define N_EDGES 600000
#define IN_CH 128
#define HID_CH 128
#define OUT_CH 64
#define NUM_GRAPHS 512

// ---------------- device scratch (zero-initialized at load; every call leaves
// g_cnt / g_pool / g_pcnt zeroed again, so replays are identical) ----------------
__device__ float g_t1[N_NODES * HID_CH];       // 25.6 MB
__device__ float g_t2[N_NODES * HID_CH];       // 25.6 MB
__device__ int   g_cnt[N_NODES];
__device__ float g_dinv[N_NODES];
__device__ int   g_rowptr[N_NODES + 1];
__device__ int   g_cursor[N_NODES];
__device__ int   g_csrsrc[N_EDGES];
__device__ float g_pool[NUM_GRAPHS * HID_CH];
__device__ float g_pcnt[NUM_GRAPHS];
__device__ __nv_bfloat16 g_wh[HID_CH * HID_CH];   // W^T hi, [n][k]
__device__ __nv_bfloat16 g_wl[HID_CH * HID_CH];   // W^T lo, [n][k]

__device__ __forceinline__ void split_bf16(float x, unsigned short& h, unsigned short& l) {
    __nv_bfloat16 hb = __float2bfloat16_rn(x);
    float r = x - __bfloat162float(hb);
    __nv_bfloat16 lb = __float2bfloat16_rn(r);
    h = __bfloat16_as_ushort(hb);
    l = __bfloat16_as_ushort(lb);
}

// ---------------- histogram of in-degrees (real edges only) ----------------
__global__ void hist_kernel(const int* __restrict__ dst) {
    int i = blockIdx.x * blockDim.x + threadIdx.x;
    if (i < N_EDGES) atomicAdd(&g_cnt[dst[i]], 1);
}

// ---------------- single-block scan -> rowptr, cursor, dinv; re-zeroes g_cnt ----------------
__global__ void scan_kernel() {
    __shared__ int part[1024];
    const int tid = threadIdx.x;
    const int chunk = (N_NODES + 1023) / 1024;   // 49
    int start = tid * chunk;
    int end = start + chunk; if (end > N_NODES) end = N_NODES;
    int s = 0;
    for (int i = start; i < end; i++) s += g_cnt[i];
    part[tid] = s;
    __syncthreads();
    for (int off = 1; off < 1024; off <<= 1) {
        int v = 0;
        if (tid >= off) v = part[tid - off];
        __syncthreads();
        part[tid] += v;
        __syncthreads();
    }
    int run = (tid == 0) ? 0 : part[tid - 1];
    for (int i = start; i < end; i++) {
        int c = g_cnt[i];
        g_cnt[i] = 0;                           // ready for next call
        g_rowptr[i] = run;
        g_cursor[i] = run;
        g_dinv[i] = rsqrtf((float)(c + 1));     // +1 self-loop
        run += c;
    }
    if (tid == 1023) g_rowptr[N_NODES] = part[1023];
}

// ---------------- fill CSR (src indices grouped by dst) ----------------
__global__ void fill_kernel(const int* __restrict__ src,
                            const int* __restrict__ dst) {
    int i = blockIdx.x * blockDim.x + threadIdx.x;
    if (i < N_EDGES) {
        int d = dst[i];
        int pos = atomicAdd(&g_cursor[d], 1);
        g_csrsrc[pos] = src[i];
    }
}

// ---------------- W split+transpose: W[k][n] f32 -> g_wh/g_wl[n][k] bf16 ----------------
__global__ void split_w(const float* __restrict__ W) {
    int i = blockIdx.x * blockDim.x + threadIdx.x;   // 16384
    int k = i >> 7, n = i & 127;
    unsigned short h, l;
    split_bf16(W[i], h, l);
    g_wh[n * 128 + k] = __ushort_as_bfloat16(h);
    g_wl[n * 128 + k] = __ushort_as_bfloat16(l);
}

// ============ tensor-core GEMM via wmma: C[row] = (A[row] @ W) * dinv[row] ============
// 64x128 output tile per CTA, 256 threads = 8 warps in a 2(M)x4(N) grid, 32x32/warp.
// bf16 hi/lo split, 3 passes (Ah*Bh + Ah*Bl + Al*Bh), fp32 accumulators.
#define KP 136                                  // padded K stride in bf16 elements
// smem: Ah(64*KP) Al(64*KP) Bh(128*KP) Bl(128*KP) bf16 = 104448 B -> 2 CTAs/SM
#define SMEM_TC ((64 + 64 + 128 + 128) * KP * 2)

__global__ __launch_bounds__(256, 2)
void gemm_tc(const float* __restrict__ A,
             const float* __restrict__ dinv, float* __restrict__ C, int M) {
    extern __shared__ char smc[];
    __nv_bfloat16* Ah = (__nv_bfloat16*)smc;
    __nv_bfloat16* Al = Ah + 64 * KP;
    __nv_bfloat16* Bh = Al + 64 * KP;
    __nv_bfloat16* Bl = Bh + 128 * KP;

    const int tid = threadIdx.x;
    const int row0 = blockIdx.x * 64;

    // ---- stage A (hi/lo split), [r][k] row-major, padded ----
    const float4* A4 = (const float4*)A;
    for (int idx = tid; idx < 64 * 32; idx += 256) {
        int r = idx >> 5;
        int kq = idx & 31;                       // float4 index along k
        int row = row0 + r;
        float4 v = make_float4(0.f, 0.f, 0.f, 0.f);
        if (row < M) v = A4[row * 32 + kq];
        unsigned short h0, h1, h2, h3, l0, l1, l2, l3;
        split_bf16(v.x, h0, l0); split_bf16(v.y, h1, l1);
        split_bf16(v.z, h2, l2); split_bf16(v.w, h3, l3);
        int e = r * KP + kq * 4;                 // 8B-aligned element offset
        *(uint2*)&Ah[e] = make_uint2((uint32_t)h0 | ((uint32_t)h1 << 16),
                                     (uint32_t)h2 | ((uint32_t)h3 << 16));
        *(uint2*)&Al[e] = make_uint2((uint32_t)l0 | ((uint32_t)l1 << 16),
                                     (uint32_t)l2 | ((uint32_t)l3 << 16));
    }

    // ---- stage B: plain copy of pre-split W^T [n][k] bf16 ----
    {
        const uint4* whg = (const uint4*)g_wh;   // 2048 uint4 (8 bf16 each)
        const uint4* wlg = (const uint4*)g_wl;
        for (int idx = tid; idx < 2048; idx += 256) {
            int n = idx >> 4, q = idx & 15;
            *(uint4*)&Bh[n * KP + q * 8] = whg[idx];
            *(uint4*)&Bl[n * KP + q * 8] = wlg[idx];
        }
    }
    __syncthreads();

    // ---- wmma main loops: warp (wm, wn) owns rows wm*32..+32, cols wn*32..+32 ----
    const int wid = tid >> 5;
    const int wm = wid & 1;
    const int wn = wid >> 1;

    wmma::fragment<wmma::accumulator, 16, 16, 16, float> cf[2][2];
#pragma unroll
    for (int i = 0; i < 2; i++)
#pragma unroll
        for (int j = 0; j < 2; j++) wmma::fill_fragment(cf[i][j], 0.0f);

#pragma unroll
    for (int p = 0; p < 3; p++) {
        const __nv_bfloat16* Ap = (p == 2) ? Al : Ah;
        const __nv_bfloat16* Bp = (p == 1) ? Bl : Bh;
#pragma unroll
        for (int k8 = 0; k8 < 8; k8++) {
            wmma::fragment<wmma::matrix_a, 16, 16, 16, __nv_bfloat16, wmma::row_major> a0, a1;
            wmma::load_matrix_sync(a0, Ap + (wm * 32 + 0)  * KP + k8 * 16, KP);
            wmma::load_matrix_sync(a1, Ap + (wm * 32 + 16) * KP + k8 * 16, KP);
            wmma::fragment<wmma::matrix_b, 16, 16, 16, __nv_bfloat16, wmma::col_major> b0, b1;
            wmma::load_matrix_sync(b0, Bp + (wn * 32 + 0)  * KP + k8 * 16, KP);
            wmma::load_matrix_sync(b1, Bp + (wn * 32 + 16) * KP + k8 * 16, KP);
            wmma::mma_sync(cf[0][0], a0, b0, cf[0][0]);
            wmma::mma_sync(cf[0][1], a0, b1, cf[0][1]);
            wmma::mma_sync(cf[1][0], a1, b0, cf[1][0]);
            wmma::mma_sync(cf[1][1], a1, b1, cf[1][1]);
        }
    }

    __syncthreads();                             // done reading A smem; reuse for C
    float* cs = (float*)smc;                     // 64x128 f32 = 32KB (fits in Ah+Al)
#pragma unroll
    for (int i = 0; i < 2; i++)
#pragma unroll
        for (int j = 0; j < 2; j++)
            wmma::store_matrix_sync(&cs[(wm * 32 + i * 16) * 128 + wn * 32 + j * 16],
                                    cf[i][j], 128, wmma::mem_row_major);
    __syncthreads();

    // ---- epilogue: scale by dinv[row], write out ----
    float4* C4 = (float4*)C;
    const float4* cs4 = (const float4*)cs;
    for (int idx = tid; idx < 64 * 32; idx += 256) {
        int r = idx >> 5, cq = idx & 31;
        int row = row0 + r;
        if (row < M) {
            float dv = dinv[row];
            float4 v = cs4[r * 32 + cq];
            v.x *= dv; v.y *= dv; v.z *= dv; v.w *= dv;
            C4[row * 32 + cq] = v;
        }
    }
}

// ---------------- aggregation on pre-scaled features h' = (xW)*dinv ----------------
// out[d] = relu(dinv[d] * (sum_{s in N(d)} h'[s] + h'[d]) + b)
__global__ void agg_kernel(const float* __restrict__ hin,
                           float* __restrict__ hout,
                           const float* __restrict__ bias) {
    int gid = blockIdx.x * blockDim.x + threadIdx.x;
    int node = gid >> 5;
    int lane = gid & 31;
    if (node >= N_NODES) return;

    const float dv = g_dinv[node];
    const float4* h4 = (const float4*)hin;

    float4 acc = __ldg(&h4[node * 32 + lane]);   // self-loop (pre-scaled)

    int e0 = g_rowptr[node];
    int e1 = g_rowptr[node + 1];
    int e = e0;
    for (; e + 4 <= e1; e += 4) {
        int s0 = g_csrsrc[e], s1 = g_csrsrc[e + 1], s2 = g_csrsrc[e + 2], s3 = g_csrsrc[e + 3];
        float4 v0 = __ldg(&h4[s0 * 32 + lane]);
        float4 v1 = __ldg(&h4[s1 * 32 + lane]);
        float4 v2 = __ldg(&h4[s2 * 32 + lane]);
        float4 v3 = __ldg(&h4[s3 * 32 + lane]);
        acc.x += v0.x + v1.x + v2.x + v3.x;
        acc.y += v0.y + v1.y + v2.y + v3.y;
        acc.z += v0.z + v1.z + v2.z + v3.z;
        acc.w += v0.w + v1.w + v2.w + v3.w;
    }
    for (; e < e1; e++) {
        int s = g_csrsrc[e];
        float4 v = __ldg(&h4[s * 32 + lane]);
        acc.x += v.x; acc.y += v.y; acc.z += v.z; acc.w += v.w;
    }

    float4 b = ((const float4*)bias)[lane];
    acc.x = fmaxf(acc.x * dv + b.x, 0.0f);
    acc.y = fmaxf(acc.y * dv + b.y, 0.0f);
    acc.z = fmaxf(acc.z * dv + b.z, 0.0f);
    acc.w = fmaxf(acc.w * dv + b.w, 0.0f);
    ((float4*)hout)[node * 32 + lane] = acc;
}

// ---------------- layer-2 aggregation fused with mean-pool accumulation ----------------
__global__ void agg_pool_kernel(const float* __restrict__ hin,
                                const float* __restrict__ bias,
                                const int* __restrict__ batch) {
    int gid = blockIdx.x * blockDim.x + threadIdx.x;
    int node = gid >> 5;
    int lane = gid & 31;
    if (node >= N_NODES) return;

    const float dv = g_dinv[node];
    const float4* h4 = (const float4*)hin;

    float4 acc = __ldg(&h4[node * 32 + lane]);

    int e0 = g_rowptr[node];
    int e1 = g_rowptr[node + 1];
    int e = e0;
    for (; e + 4 <= e1; e += 4) {
        int s0 = g_csrsrc[e], s1 = g_csrsrc[e + 1], s2 = g_csrsrc[e + 2], s3 = g_csrsrc[e + 3];
        float4 v0 = __ldg(&h4[s0 * 32 + lane]);
        float4 v1 = __ldg(&h4[s1 * 32 + lane]);
        float4 v2 = __ldg(&h4[s2 * 32 + lane]);
        float4 v3 = __ldg(&h4[s3 * 32 + lane]);
        acc.x += v0.x + v1.x + v2.x + v3.x;
        acc.y += v0.y + v1.y + v2.y + v3.y;
        acc.z += v0.z + v1.z + v2.z + v3.z;
        acc.w += v0.w + v1.w + v2.w + v3.w;
    }
    for (; e < e1; e++) {
        int s = g_csrsrc[e];
        float4 v = __ldg(&h4[s * 32 + lane]);
        acc.x += v.x; acc.y += v.y; acc.z += v.z; acc.w += v.w;
    }

    float4 b = ((const float4*)bias)[lane];
    int g = batch[node];
    float* p = &g_pool[g * 128 + lane * 4];
    atomicAdd(p + 0, fmaxf(acc.x * dv + b.x, 0.0f));
    atomicAdd(p + 1, fmaxf(acc.y * dv + b.y, 0.0f));
    atomicAdd(p + 2, fmaxf(acc.z * dv + b.z, 0.0f));
    atomicAdd(p + 3, fmaxf(acc.w * dv + b.w, 0.0f));
    if (lane == 0) atomicAdd(&g_pcnt[g], 1.0f);
}

// ---------------- final: out[512,64] = (pool/cnt) @ Wlin + blin; re-zero pool ----------------
__global__ void final_kernel(const float* __restrict__ Wlin,
                             const float* __restrict__ blin,
                             float* __restrict__ out) {
    __shared__ float ws[HID_CH * OUT_CH];
    __shared__ float bs[OUT_CH];
    for (int i = threadIdx.x; i < HID_CH * OUT_CH; i += 256) ws[i] = Wlin[i];
    if (threadIdx.x < OUT_CH) bs[threadIdx.x] = blin[threadIdx.x];
    __syncthreads();

    int t = blockIdx.x * 256 + threadIdx.x;    // block owns graphs [b*4, b*4+4)
    int g = t >> 6, o = t & 63;
    float inv = 1.0f / fmaxf(g_pcnt[g], 1.0f);
    float s = 0.0f;
#pragma unroll 8
    for (int k = 0; k < 128; k++)
        s += g_pool[g * 128 + k] * ws[k * 64 + o];
    out[t] = s * inv + bs[o];

    __syncthreads();   // all reads of this block's g_pool graphs done
    int base = blockIdx.x * 512;               // 4 graphs * 128 ch
    g_pool[base + threadIdx.x] = 0.0f;
    g_pool[base + 256 + threadIdx.x] = 0.0f;
    if (threadIdx.x < 4) g_pcnt[blockIdx.x * 4 + threadIdx.x] = 0.0f;
}

// ---------------- launch ----------------
extern "C" void kernel_launch(void* const* d_in, const int* in_sizes, int n_in,
                              void* d_out, int out_size) {
    const float* x    = (const float*)d_in[0];
    const float* W1   = (const float*)d_in[1];
    const float* b1   = (const float*)d_in[2];
    const float* W2   = (const float*)d_in[3];
    const float* b2   = (const float*)d_in[4];
    const float* Wlin = (const float*)d_in[5];
    const float* blin = (const float*)d_in[6];
    const int* edge   = (const int*)d_in[7];     // JAX x64-disabled: int64 -> int32
    const int* batch  = (const int*)d_in[8];
    float* out = (float*)d_out;

    const int* src = edge;
    const int* dst = edge + N_EDGES;

    float *t1, *t2, *dinv;
    cudaGetSymbolAddress((void**)&t1, g_t1);
    cudaGetSymbolAddress((void**)&t2, g_t2);
    cudaGetSymbolAddress((void**)&dinv, g_dinv);

    cudaFuncSetAttribute(gemm_tc, cudaFuncAttributeMaxDynamicSharedMemorySize, SMEM_TC);

    const int eb = (N_EDGES + 255) / 256;               // 2344
    const int gb = (N_NODES + 63) / 64;                 // 782
    const int ab = (N_NODES * 32) / 256;                // 6250

    hist_kernel<<<eb, 256>>>(dst);
    scan_kernel<<<1, 1024>>>();
    fill_kernel<<<eb, 256>>>(src, dst);

    split_w<<<64, 256>>>(W1);
    gemm_tc<<<gb, 256, SMEM_TC>>>(x, dinv, t1, N_NODES);
    agg_kernel<<<ab, 256>>>(t1, t2, b1);

    split_w<<<64, 256>>>(W2);
    gemm_tc<<<gb, 256, SMEM_TC>>>(t2, dinv, t1, N_NODES);
    agg_pool_kernel<<<ab, 256>>>(t1, b2, batch);

    final_kernel<<<128, 256>>>(Wlin, blin, out);
}

// round 7
// speedup vs baseline: 1.0892x; 1.0041x over previous
#include <cuda_runtime.h>
#include <cuda_bf16.h>
#include <mma.h>
#include <cstdint>

using namespace nvcuda;

#define N_NODES 50000
#define N_EDGES 600000
#define IN_CH 128
#define HID_CH 128
#define OUT_CH 64
#define NUM_GRAPHS 512

// ---------------- device scratch (zero-initialized at load; every call leaves
// g_cnt / g_pool / g_pcnt zeroed again, so replays are identical) ----------------
__device__ float g_t1[N_NODES * HID_CH];       // 25.6 MB
__device__ float g_t2[N_NODES * HID_CH];       // 25.6 MB
__device__ int   g_cnt[N_NODES];
__device__ float g_dinv[N_NODES];
__device__ int   g_rowptr[N_NODES + 1];
__device__ int   g_cursor[N_NODES];
__device__ int   g_csrsrc[N_EDGES];
__device__ float g_pool[NUM_GRAPHS * HID_CH];
__device__ float g_pcnt[NUM_GRAPHS];
__device__ __nv_bfloat16 g_wh1[HID_CH * HID_CH];   // W1^T hi, [n][k]
__device__ __nv_bfloat16 g_wl1[HID_CH * HID_CH];   // W1^T lo
__device__ __nv_bfloat16 g_wh2[HID_CH * HID_CH];   // W2^T hi
__device__ __nv_bfloat16 g_wl2[HID_CH * HID_CH];   // W2^T lo

__device__ __forceinline__ void split_bf16(float x, unsigned short& h, unsigned short& l) {
    __nv_bfloat16 hb = __float2bfloat16_rn(x);
    float r = x - __bfloat162float(hb);
    __nv_bfloat16 lb = __float2bfloat16_rn(r);
    h = __bfloat16_as_ushort(hb);
    l = __bfloat16_as_ushort(lb);
}

// ---------------- histogram of in-degrees (real edges only) ----------------
__global__ void hist_kernel(const int* __restrict__ dst) {
    int i = blockIdx.x * blockDim.x + threadIdx.x;
    if (i < N_EDGES) atomicAdd(&g_cnt[dst[i]], 1);
}

// ---------------- single-block scan -> rowptr, cursor, dinv; re-zeroes g_cnt ----------------
__global__ void scan_kernel() {
    __shared__ int part[1024];
    const int tid = threadIdx.x;
    const int chunk = (N_NODES + 1023) / 1024;   // 49
    int start = tid * chunk;
    int end = start + chunk; if (end > N_NODES) end = N_NODES;
    int s = 0;
    for (int i = start; i < end; i++) s += g_cnt[i];
    part[tid] = s;
    __syncthreads();
    for (int off = 1; off < 1024; off <<= 1) {
        int v = 0;
        if (tid >= off) v = part[tid - off];
        __syncthreads();
        part[tid] += v;
        __syncthreads();
    }
    int run = (tid == 0) ? 0 : part[tid - 1];
    for (int i = start; i < end; i++) {
        int c = g_cnt[i];
        g_cnt[i] = 0;                           // ready for next call
        g_rowptr[i] = run;
        g_cursor[i] = run;
        g_dinv[i] = rsqrtf((float)(c + 1));     // +1 self-loop
        run += c;
    }
    if (tid == 1023) g_rowptr[N_NODES] = part[1023];
}

// ---------------- fill CSR (src indices grouped by dst) ----------------
__global__ void fill_kernel(const int* __restrict__ src,
                            const int* __restrict__ dst) {
    int i = blockIdx.x * blockDim.x + threadIdx.x;
    if (i < N_EDGES) {
        int d = dst[i];
        int pos = atomicAdd(&g_cursor[d], 1);
        g_csrsrc[pos] = src[i];
    }
}

// ---------------- W split+transpose for BOTH layers in one launch ----------------
__global__ void split_w_both(const float* __restrict__ W1,
                             const float* __restrict__ W2) {
    int i = blockIdx.x * blockDim.x + threadIdx.x;   // 32768
    unsigned short h, l;
    if (i < 16384) {
        int k = i >> 7, n = i & 127;
        split_bf16(W1[i], h, l);
        g_wh1[n * 128 + k] = __ushort_as_bfloat16(h);
        g_wl1[n * 128 + k] = __ushort_as_bfloat16(l);
    } else {
        int j = i - 16384;
        int k = j >> 7, n = j & 127;
        split_bf16(W2[j], h, l);
        g_wh2[n * 128 + k] = __ushort_as_bfloat16(h);
        g_wl2[n * 128 + k] = __ushort_as_bfloat16(l);
    }
}

// ============ tensor-core GEMM via wmma: C[row] = (A[row] @ W) * dinv[row] ============
// 64x128 output tile per CTA, 256 threads = 8 warps in a 2(M)x4(N) grid, 32x32/warp.
// bf16 hi/lo split, 3 passes (Ah*Bh + Ah*Bl + Al*Bh), fp32 accumulators.
#define KP 136                                  // padded K stride in bf16 elements
// smem: Ah(64*KP) Al(64*KP) Bh(128*KP) Bl(128*KP) bf16 = 104448 B -> 2 CTAs/SM
#define SMEM_TC ((64 + 64 + 128 + 128) * KP * 2)

__global__ __launch_bounds__(256, 2)
void gemm_tc(const float* __restrict__ A,
             const __nv_bfloat16* __restrict__ wh,
             const __nv_bfloat16* __restrict__ wl,
             const float* __restrict__ dinv, float* __restrict__ C, int M) {
    extern __shared__ char smc[];
    __nv_bfloat16* Ah = (__nv_bfloat16*)smc;
    __nv_bfloat16* Al = Ah + 64 * KP;
    __nv_bfloat16* Bh = Al + 64 * KP;
    __nv_bfloat16* Bl = Bh + 128 * KP;

    const int tid = threadIdx.x;
    const int row0 = blockIdx.x * 64;

    // ---- stage A (hi/lo split), [r][k] row-major, padded ----
    const float4* A4 = (const float4*)A;
    for (int idx = tid; idx < 64 * 32; idx += 256) {
        int r = idx >> 5;
        int kq = idx & 31;                       // float4 index along k
        int row = row0 + r;
        float4 v = make_float4(0.f, 0.f, 0.f, 0.f);
        if (row < M) v = A4[row * 32 + kq];
        unsigned short h0, h1, h2, h3, l0, l1, l2, l3;
        split_bf16(v.x, h0, l0); split_bf16(v.y, h1, l1);
        split_bf16(v.z, h2, l2); split_bf16(v.w, h3, l3);
        int e = r * KP + kq * 4;                 // 8B-aligned element offset
        *(uint2*)&Ah[e] = make_uint2((uint32_t)h0 | ((uint32_t)h1 << 16),
                                     (uint32_t)h2 | ((uint32_t)h3 << 16));
        *(uint2*)&Al[e] = make_uint2((uint32_t)l0 | ((uint32_t)l1 << 16),
                                     (uint32_t)l2 | ((uint32_t)l3 << 16));
    }

    // ---- stage B: plain copy of pre-split W^T [n][k] bf16 ----
    {
        const uint4* whg = (const uint4*)wh;     // 2048 uint4 (8 bf16 each)
        const uint4* wlg = (const uint4*)wl;
        for (int idx = tid; idx < 2048; idx += 256) {
            int n = idx >> 4, q = idx & 15;
            *(uint4*)&Bh[n * KP + q * 8] = whg[idx];
            *(uint4*)&Bl[n * KP + q * 8] = wlg[idx];
        }
    }
    __syncthreads();

    // ---- wmma main loops: warp (wm, wn) owns rows wm*32..+32, cols wn*32..+32 ----
    const int wid = tid >> 5;
    const int wm = wid & 1;
    const int wn = wid >> 1;

    wmma::fragment<wmma::accumulator, 16, 16, 16, float> cf[2][2];
#pragma unroll
    for (int i = 0; i < 2; i++)
#pragma unroll
        for (int j = 0; j < 2; j++) wmma::fill_fragment(cf[i][j], 0.0f);

#pragma unroll
    for (int p = 0; p < 3; p++) {
        const __nv_bfloat16* Ap = (p == 2) ? Al : Ah;
        const __nv_bfloat16* Bp = (p == 1) ? Bl : Bh;
#pragma unroll
        for (int k8 = 0; k8 < 8; k8++) {
            wmma::fragment<wmma::matrix_a, 16, 16, 16, __nv_bfloat16, wmma::row_major> a0, a1;
            wmma::load_matrix_sync(a0, Ap + (wm * 32 + 0)  * KP + k8 * 16, KP);
            wmma::load_matrix_sync(a1, Ap + (wm * 32 + 16) * KP + k8 * 16, KP);
            wmma::fragment<wmma::matrix_b, 16, 16, 16, __nv_bfloat16, wmma::col_major> b0, b1;
            wmma::load_matrix_sync(b0, Bp + (wn * 32 + 0)  * KP + k8 * 16, KP);
            wmma::load_matrix_sync(b1, Bp + (wn * 32 + 16) * KP + k8 * 16, KP);
            wmma::mma_sync(cf[0][0], a0, b0, cf[0][0]);
            wmma::mma_sync(cf[0][1], a0, b1, cf[0][1]);
            wmma::mma_sync(cf[1][0], a1, b0, cf[1][0]);
            wmma::mma_sync(cf[1][1], a1, b1, cf[1][1]);
        }
    }

    __syncthreads();                             // done reading A smem; reuse for C
    float* cs = (float*)smc;                     // 64x128 f32 = 32KB (fits in Ah+Al)
#pragma unroll
    for (int i = 0; i < 2; i++)
#pragma unroll
        for (int j = 0; j < 2; j++)
            wmma::store_matrix_sync(&cs[(wm * 32 + i * 16) * 128 + wn * 32 + j * 16],
                                    cf[i][j], 128, wmma::mem_row_major);
    __syncthreads();

    // ---- epilogue: scale by dinv[row], write out ----
    float4* C4 = (float4*)C;
    const float4* cs4 = (const float4*)cs;
    for (int idx = tid; idx < 64 * 32; idx += 256) {
        int r = idx >> 5, cq = idx & 31;
        int row = row0 + r;
        if (row < M) {
            float dv = dinv[row];
            float4 v = cs4[r * 32 + cq];
            v.x *= dv; v.y *= dv; v.z *= dv; v.w *= dv;
            C4[row * 32 + cq] = v;
        }
    }
}

// ---------------- aggregation on pre-scaled features h' = (xW)*dinv ----------------
// out[d] = relu(dinv[d] * (sum_{s in N(d)} h'[s] + h'[d]) + b)
__global__ void agg_kernel(const float* __restrict__ hin,
                           float* __restrict__ hout,
                           const float* __restrict__ bias) {
    int gid = blockIdx.x * blockDim.x + threadIdx.x;
    int node = gid >> 5;
    int lane = gid & 31;
    if (node >= N_NODES) return;

    const float dv = g_dinv[node];
    const float4* h4 = (const float4*)hin;

    float4 acc = __ldg(&h4[node * 32 + lane]);   // self-loop (pre-scaled)

    int e0 = g_rowptr[node];
    int e1 = g_rowptr[node + 1];
    int e = e0;
    for (; e + 4 <= e1; e += 4) {
        int s0 = g_csrsrc[e], s1 = g_csrsrc[e + 1], s2 = g_csrsrc[e + 2], s3 = g_csrsrc[e + 3];
        float4 v0 = __ldg(&h4[s0 * 32 + lane]);
        float4 v1 = __ldg(&h4[s1 * 32 + lane]);
        float4 v2 = __ldg(&h4[s2 * 32 + lane]);
        float4 v3 = __ldg(&h4[s3 * 32 + lane]);
        acc.x += v0.x + v1.x + v2.x + v3.x;
        acc.y += v0.y + v1.y + v2.y + v3.y;
        acc.z += v0.z + v1.z + v2.z + v3.z;
        acc.w += v0.w + v1.w + v2.w + v3.w;
    }
    for (; e < e1; e++) {
        int s = g_csrsrc[e];
        float4 v = __ldg(&h4[s * 32 + lane]);
        acc.x += v.x; acc.y += v.y; acc.z += v.z; acc.w += v.w;
    }

    float4 b = ((const float4*)bias)[lane];
    acc.x = fmaxf(acc.x * dv + b.x, 0.0f);
    acc.y = fmaxf(acc.y * dv + b.y, 0.0f);
    acc.z = fmaxf(acc.z * dv + b.z, 0.0f);
    acc.w = fmaxf(acc.w * dv + b.w, 0.0f);
    ((float4*)hout)[node * 32 + lane] = acc;
}

// ---------------- layer-2 aggregation fused with mean-pool accumulation ----------------
__global__ void agg_pool_kernel(const float* __restrict__ hin,
                                const float* __restrict__ bias,
                                const int* __restrict__ batch) {
    int gid = blockIdx.x * blockDim.x + threadIdx.x;
    int node = gid >> 5;
    int lane = gid & 31;
    if (node >= N_NODES) return;

    const float dv = g_dinv[node];
    const float4* h4 = (const float4*)hin;

    float4 acc = __ldg(&h4[node * 32 + lane]);

    int e0 = g_rowptr[node];
    int e1 = g_rowptr[node + 1];
    int e = e0;
    for (; e + 4 <= e1; e += 4) {
        int s0 = g_csrsrc[e], s1 = g_csrsrc[e + 1], s2 = g_csrsrc[e + 2], s3 = g_csrsrc[e + 3];
        float4 v0 = __ldg(&h4[s0 * 32 + lane]);
        float4 v1 = __ldg(&h4[s1 * 32 + lane]);
        float4 v2 = __ldg(&h4[s2 * 32 + lane]);
        float4 v3 = __ldg(&h4[s3 * 32 + lane]);
        acc.x += v0.x + v1.x + v2.x + v3.x;
        acc.y += v0.y + v1.y + v2.y + v3.y;
        acc.z += v0.z + v1.z + v2.z + v3.z;
        acc.w += v0.w + v1.w + v2.w + v3.w;
    }
    for (; e < e1; e++) {
        int s = g_csrsrc[e];
        float4 v = __ldg(&h4[s * 32 + lane]);
        acc.x += v.x; acc.y += v.y; acc.z += v.z; acc.w += v.w;
    }

    float4 b = ((const float4*)bias)[lane];
    int g = batch[node];
    float* p = &g_pool[g * 128 + lane * 4];
    atomicAdd(p + 0, fmaxf(acc.x * dv + b.x, 0.0f));
    atomicAdd(p + 1, fmaxf(acc.y * dv + b.y, 0.0f));
    atomicAdd(p + 2, fmaxf(acc.z * dv + b.z, 0.0f));
    atomicAdd(p + 3, fmaxf(acc.w * dv + b.w, 0.0f));
    if (lane == 0) atomicAdd(&g_pcnt[g], 1.0f);
}

// ---------------- final: out[512,64] = (pool/cnt) @ Wlin + blin; re-zero pool ----------------
__global__ void final_kernel(const float* __restrict__ Wlin,
                             const float* __restrict__ blin,
                             float* __restrict__ out) {
    __shared__ float ws[HID_CH * OUT_CH];
    __shared__ float bs[OUT_CH];
    for (int i = threadIdx.x; i < HID_CH * OUT_CH; i += 256) ws[i] = Wlin[i];
    if (threadIdx.x < OUT_CH) bs[threadIdx.x] = blin[threadIdx.x];
    __syncthreads();

    int t = blockIdx.x * 256 + threadIdx.x;    // block owns graphs [b*4, b*4+4)
    int g = t >> 6, o = t & 63;
    float inv = 1.0f / fmaxf(g_pcnt[g], 1.0f);
    float s = 0.0f;
#pragma unroll 8
    for (int k = 0; k < 128; k++)
        s += g_pool[g * 128 + k] * ws[k * 64 + o];
    out[t] = s * inv + bs[o];

    __syncthreads();   // all reads of this block's g_pool graphs done
    int base = blockIdx.x * 512;               // 4 graphs * 128 ch
    g_pool[base + threadIdx.x] = 0.0f;
    g_pool[base + 256 + threadIdx.x] = 0.0f;
    if (threadIdx.x < 4) g_pcnt[blockIdx.x * 4 + threadIdx.x] = 0.0f;
}

// ---------------- launch (fork-join: CSR build overlaps split_w + GEMM1) ----------------
extern "C" void kernel_launch(void* const* d_in, const int* in_sizes, int n_in,
                              void* d_out, int out_size) {
    const float* x    = (const float*)d_in[0];
    const float* W1   = (const float*)d_in[1];
    const float* b1   = (const float*)d_in[2];
    const float* W2   = (const float*)d_in[3];
    const float* b2   = (const float*)d_in[4];
    const float* Wlin = (const float*)d_in[5];
    const float* blin = (const float*)d_in[6];
    const int* edge   = (const int*)d_in[7];     // JAX x64-disabled: int64 -> int32
    const int* batch  = (const int*)d_in[8];
    float* out = (float*)d_out;

    const int* src = edge;
    const int* dst = edge + N_EDGES;

    float *t1, *t2, *dinv;
    __nv_bfloat16 *wh1, *wl1, *wh2, *wl2;
    cudaGetSymbolAddress((void**)&t1, g_t1);
    cudaGetSymbolAddress((void**)&t2, g_t2);
    cudaGetSymbolAddress((void**)&dinv, g_dinv);
    cudaGetSymbolAddress((void**)&wh1, g_wh1);
    cudaGetSymbolAddress((void**)&wl1, g_wl1);
    cudaGetSymbolAddress((void**)&wh2, g_wh2);
    cudaGetSymbolAddress((void**)&wl2, g_wl2);

    cudaFuncSetAttribute(gemm_tc, cudaFuncAttributeMaxDynamicSharedMemorySize, SMEM_TC);

    // host-side stream/event handles, created once (no device memory involved)
    static cudaStream_t s_side = nullptr;
    static cudaEvent_t ev_fork = nullptr, ev_join = nullptr;
    if (s_side == nullptr) {
        cudaStreamCreateWithFlags(&s_side, cudaStreamNonBlocking);
        cudaEventCreateWithFlags(&ev_fork, cudaEventDisableTiming);
        cudaEventCreateWithFlags(&ev_join, cudaEventDisableTiming);
    }

    const int eb = (N_EDGES + 255) / 256;               // 2344
    const int gb = (N_NODES + 63) / 64;                 // 782
    const int ab = (N_NODES * 32) / 256;                // 6250

    // fork: CSR build on side stream, concurrent with split_w + GEMM1
    cudaEventRecord(ev_fork, 0);
    cudaStreamWaitEvent(s_side, ev_fork, 0);
    hist_kernel<<<eb, 256, 0, s_side>>>(dst);
    scan_kernel<<<1, 1024, 0, s_side>>>();
    fill_kernel<<<eb, 256, 0, s_side>>>(src, dst);
    cudaEventRecord(ev_join, s_side);

    // main stream: weight split + layer-1 GEMM (needs only x, W; dinv comes from
    // scan which must complete before gemm_tc reads it -> gemm needs dinv!
    // dinv is produced by scan_kernel on the side stream; therefore GEMM1 must
    // not scale by dinv... instead GEMM1 runs WITHOUT the dinv dependency:
    // we keep dinv in the epilogue, so GEMM1 must wait on scan. To preserve the
    // overlap, only split_w overlaps the full CSR chain and GEMM1 waits on join.
    split_w_both<<<128, 256>>>(W1, W2);
    cudaStreamWaitEvent(0, ev_join, 0);

    gemm_tc<<<gb, 256, SMEM_TC>>>(x, wh1, wl1, dinv, t1, N_NODES);
    agg_kernel<<<ab, 256>>>(t1, t2, b1);

    gemm_tc<<<gb, 256, SMEM_TC>>>(t2, wh2, wl2, dinv, t1, N_NODES);
    agg_pool_kernel<<<ab, 256>>>(t1, b2, batch);

    final_kernel<<<128, 256>>>(Wlin, blin, out);
}

// round 8
// speedup vs baseline: 1.2778x; 1.1731x over previous
#include <cuda_runtime.h>
#include <cuda_bf16.h>
#include <mma.h>
#include <cstdint>

using namespace nvcuda;

#define N_NODES 50000
#define N_EDGES 600000
#define IN_CH 128
#define HID_CH 128
#define OUT_CH 64
#define NUM_GRAPHS 512

// ---------------- device scratch (zero-initialized at load; every call leaves
// g_cnt / g_pool / g_pcnt zeroed again, so replays are identical) ----------------
__device__ float g_t1[N_NODES * HID_CH];       // 25.6 MB
__device__ float g_t2[N_NODES * HID_CH];       // 25.6 MB
__device__ int   g_cnt[N_NODES];
__device__ float g_dinv[N_NODES];
__device__ int   g_rowptr[N_NODES + 1];
__device__ int   g_cursor[N_NODES];
__device__ int   g_csrsrc[N_EDGES];
__device__ float g_pool[NUM_GRAPHS * HID_CH];
__device__ float g_pcnt[NUM_GRAPHS];
__device__ __nv_bfloat16 g_wh1[HID_CH * HID_CH];   // W1^T hi, [n][k]
__device__ __nv_bfloat16 g_wl1[HID_CH * HID_CH];   // W1^T lo
__device__ __nv_bfloat16 g_wh2[HID_CH * HID_CH];   // W2^T hi
__device__ __nv_bfloat16 g_wl2[HID_CH * HID_CH];   // W2^T lo

__device__ __forceinline__ void split_bf16(float x, unsigned short& h, unsigned short& l) {
    __nv_bfloat16 hb = __float2bfloat16_rn(x);
    float r = x - __bfloat162float(hb);
    __nv_bfloat16 lb = __float2bfloat16_rn(r);
    h = __bfloat16_as_ushort(hb);
    l = __bfloat16_as_ushort(lb);
}

// ---------------- histogram of in-degrees (real edges only) ----------------
__global__ void hist_kernel(const int* __restrict__ dst) {
    int i = blockIdx.x * blockDim.x + threadIdx.x;
    if (i < N_EDGES) atomicAdd(&g_cnt[dst[i]], 1);
}

// ---------------- single-block scan -> rowptr, cursor, dinv; re-zeroes g_cnt ----------------
__global__ void scan_kernel() {
    __shared__ int part[1024];
    const int tid = threadIdx.x;
    const int chunk = (N_NODES + 1023) / 1024;   // 49
    int start = tid * chunk;
    int end = start + chunk; if (end > N_NODES) end = N_NODES;
    int s = 0;
    for (int i = start; i < end; i++) s += g_cnt[i];
    part[tid] = s;
    __syncthreads();
    for (int off = 1; off < 1024; off <<= 1) {
        int v = 0;
        if (tid >= off) v = part[tid - off];
        __syncthreads();
        part[tid] += v;
        __syncthreads();
    }
    int run = (tid == 0) ? 0 : part[tid - 1];
    for (int i = start; i < end; i++) {
        int c = g_cnt[i];
        g_cnt[i] = 0;                           // ready for next call
        g_rowptr[i] = run;
        g_cursor[i] = run;
        g_dinv[i] = rsqrtf((float)(c + 1));     // +1 self-loop
        run += c;
    }
    if (tid == 1023) g_rowptr[N_NODES] = part[1023];
}

// ---------------- fill CSR (src indices grouped by dst) ----------------
__global__ void fill_kernel(const int* __restrict__ src,
                            const int* __restrict__ dst) {
    int i = blockIdx.x * blockDim.x + threadIdx.x;
    if (i < N_EDGES) {
        int d = dst[i];
        int pos = atomicAdd(&g_cursor[d], 1);
        g_csrsrc[pos] = src[i];
    }
}

// ---------------- W split+transpose for BOTH layers in one launch ----------------
__global__ void split_w_both(const float* __restrict__ W1,
                             const float* __restrict__ W2) {
    int i = blockIdx.x * blockDim.x + threadIdx.x;   // 32768
    unsigned short h, l;
    if (i < 16384) {
        int k = i >> 7, n = i & 127;
        split_bf16(W1[i], h, l);
        g_wh1[n * 128 + k] = __ushort_as_bfloat16(h);
        g_wl1[n * 128 + k] = __ushort_as_bfloat16(l);
    } else {
        int j = i - 16384;
        int k = j >> 7, n = j & 127;
        split_bf16(W2[j], h, l);
        g_wh2[n * 128 + k] = __ushort_as_bfloat16(h);
        g_wl2[n * 128 + k] = __ushort_as_bfloat16(l);
    }
}

// ============ tensor-core GEMM via wmma: C[row] = (A[row] @ W) * scale ============
// 64x128 output tile per CTA, 256 threads = 8 warps in a 2(M)x4(N) grid, 32x32/warp.
// bf16 hi/lo split, 3 passes (Ah*Bh + Ah*Bl + Al*Bh), fp32 accumulators.
// dinv == nullptr -> no epilogue scale (layer 1: runs concurrent with CSR build).
#define KP 136                                  // padded K stride in bf16 elements
// smem: Ah(64*KP) Al(64*KP) Bh(128*KP) Bl(128*KP) bf16 = 104448 B -> 2 CTAs/SM
#define SMEM_TC ((64 + 64 + 128 + 128) * KP * 2)

__global__ __launch_bounds__(256, 2)
void gemm_tc(const float* __restrict__ A,
             const __nv_bfloat16* __restrict__ wh,
             const __nv_bfloat16* __restrict__ wl,
             const float* __restrict__ dinv, float* __restrict__ C, int M) {
    extern __shared__ char smc[];
    __nv_bfloat16* Ah = (__nv_bfloat16*)smc;
    __nv_bfloat16* Al = Ah + 64 * KP;
    __nv_bfloat16* Bh = Al + 64 * KP;
    __nv_bfloat16* Bl = Bh + 128 * KP;

    const int tid = threadIdx.x;
    const int row0 = blockIdx.x * 64;

    // ---- stage A (hi/lo split), [r][k] row-major, padded ----
    const float4* A4 = (const float4*)A;
    for (int idx = tid; idx < 64 * 32; idx += 256) {
        int r = idx >> 5;
        int kq = idx & 31;                       // float4 index along k
        int row = row0 + r;
        float4 v = make_float4(0.f, 0.f, 0.f, 0.f);
        if (row < M) v = A4[row * 32 + kq];
        unsigned short h0, h1, h2, h3, l0, l1, l2, l3;
        split_bf16(v.x, h0, l0); split_bf16(v.y, h1, l1);
        split_bf16(v.z, h2, l2); split_bf16(v.w, h3, l3);
        int e = r * KP + kq * 4;                 // 8B-aligned element offset
        *(uint2*)&Ah[e] = make_uint2((uint32_t)h0 | ((uint32_t)h1 << 16),
                                     (uint32_t)h2 | ((uint32_t)h3 << 16));
        *(uint2*)&Al[e] = make_uint2((uint32_t)l0 | ((uint32_t)l1 << 16),
                                     (uint32_t)l2 | ((uint32_t)l3 << 16));
    }

    // ---- stage B: plain copy of pre-split W^T [n][k] bf16 ----
    {
        const uint4* whg = (const uint4*)wh;     // 2048 uint4 (8 bf16 each)
        const uint4* wlg = (const uint4*)wl;
        for (int idx = tid; idx < 2048; idx += 256) {
            int n = idx >> 4, q = idx & 15;
            *(uint4*)&Bh[n * KP + q * 8] = whg[idx];
            *(uint4*)&Bl[n * KP + q * 8] = wlg[idx];
        }
    }
    __syncthreads();

    // ---- wmma main loops: warp (wm, wn) owns rows wm*32..+32, cols wn*32..+32 ----
    const int wid = tid >> 5;
    const int wm = wid & 1;
    const int wn = wid >> 1;

    wmma::fragment<wmma::accumulator, 16, 16, 16, float> cf[2][2];
#pragma unroll
    for (int i = 0; i < 2; i++)
#pragma unroll
        for (int j = 0; j < 2; j++) wmma::fill_fragment(cf[i][j], 0.0f);

#pragma unroll
    for (int p = 0; p < 3; p++) {
        const __nv_bfloat16* Ap = (p == 2) ? Al : Ah;
        const __nv_bfloat16* Bp = (p == 1) ? Bl : Bh;
#pragma unroll
        for (int k8 = 0; k8 < 8; k8++) {
            wmma::fragment<wmma::matrix_a, 16, 16, 16, __nv_bfloat16, wmma::row_major> a0, a1;
            wmma::load_matrix_sync(a0, Ap + (wm * 32 + 0)  * KP + k8 * 16, KP);
            wmma::load_matrix_sync(a1, Ap + (wm * 32 + 16) * KP + k8 * 16, KP);
            wmma::fragment<wmma::matrix_b, 16, 16, 16, __nv_bfloat16, wmma::col_major> b0, b1;
            wmma::load_matrix_sync(b0, Bp + (wn * 32 + 0)  * KP + k8 * 16, KP);
            wmma::load_matrix_sync(b1, Bp + (wn * 32 + 16) * KP + k8 * 16, KP);
            wmma::mma_sync(cf[0][0], a0, b0, cf[0][0]);
            wmma::mma_sync(cf[0][1], a0, b1, cf[0][1]);
            wmma::mma_sync(cf[1][0], a1, b0, cf[1][0]);
            wmma::mma_sync(cf[1][1], a1, b1, cf[1][1]);
        }
    }

    __syncthreads();                             // done reading A smem; reuse for C
    float* cs = (float*)smc;                     // 64x128 f32 = 32KB (fits in Ah+Al)
#pragma unroll
    for (int i = 0; i < 2; i++)
#pragma unroll
        for (int j = 0; j < 2; j++)
            wmma::store_matrix_sync(&cs[(wm * 32 + i * 16) * 128 + wn * 32 + j * 16],
                                    cf[i][j], 128, wmma::mem_row_major);
    __syncthreads();

    // ---- epilogue: optional dinv scale, write out ----
    float4* C4 = (float4*)C;
    const float4* cs4 = (const float4*)cs;
    for (int idx = tid; idx < 64 * 32; idx += 256) {
        int r = idx >> 5, cq = idx & 31;
        int row = row0 + r;
        if (row < M) {
            float dv = dinv ? dinv[row] : 1.0f;
            float4 v = cs4[r * 32 + cq];
            v.x *= dv; v.y *= dv; v.z *= dv; v.w *= dv;
            C4[row * 32 + cq] = v;
        }
    }
}

// ------------- layer-1 aggregation on UNSCALED h (applies dinv[s] per edge) -------------
// out[d] = relu(dinv[d] * (sum_s h[s]*dinv[s] + h[d]*dinv[d]) + b)
__global__ void agg_scale_kernel(const float* __restrict__ hin,
                                 float* __restrict__ hout,
                                 const float* __restrict__ bias) {
    int gid = blockIdx.x * blockDim.x + threadIdx.x;
    int node = gid >> 5;
    int lane = gid & 31;
    if (node >= N_NODES) return;

    const float dv = g_dinv[node];
    const float4* h4 = (const float4*)hin;

    float4 acc = __ldg(&h4[node * 32 + lane]);   // self-loop (unscaled)
    acc.x *= dv; acc.y *= dv; acc.z *= dv; acc.w *= dv;

    int e0 = g_rowptr[node];
    int e1 = g_rowptr[node + 1];
    int e = e0;
    for (; e + 4 <= e1; e += 4) {
        int s0 = g_csrsrc[e], s1 = g_csrsrc[e + 1], s2 = g_csrsrc[e + 2], s3 = g_csrsrc[e + 3];
        float c0 = g_dinv[s0], c1 = g_dinv[s1], c2 = g_dinv[s2], c3 = g_dinv[s3];
        float4 v0 = __ldg(&h4[s0 * 32 + lane]);
        float4 v1 = __ldg(&h4[s1 * 32 + lane]);
        float4 v2 = __ldg(&h4[s2 * 32 + lane]);
        float4 v3 = __ldg(&h4[s3 * 32 + lane]);
        acc.x += v0.x * c0 + v1.x * c1 + v2.x * c2 + v3.x * c3;
        acc.y += v0.y * c0 + v1.y * c1 + v2.y * c2 + v3.y * c3;
        acc.z += v0.z * c0 + v1.z * c1 + v2.z * c2 + v3.z * c3;
        acc.w += v0.w * c0 + v1.w * c1 + v2.w * c2 + v3.w * c3;
    }
    for (; e < e1; e++) {
        int s = g_csrsrc[e];
        float c = g_dinv[s];
        float4 v = __ldg(&h4[s * 32 + lane]);
        acc.x += v.x * c; acc.y += v.y * c; acc.z += v.z * c; acc.w += v.w * c;
    }

    float4 b = ((const float4*)bias)[lane];
    acc.x = fmaxf(acc.x * dv + b.x, 0.0f);
    acc.y = fmaxf(acc.y * dv + b.y, 0.0f);
    acc.z = fmaxf(acc.z * dv + b.z, 0.0f);
    acc.w = fmaxf(acc.w * dv + b.w, 0.0f);
    ((float4*)hout)[node * 32 + lane] = acc;
}

// ------- layer-2 aggregation (pre-scaled h' = (hW)*dinv) fused with mean-pool -------
__global__ void agg_pool_kernel(const float* __restrict__ hin,
                                const float* __restrict__ bias,
                                const int* __restrict__ batch) {
    int gid = blockIdx.x * blockDim.x + threadIdx.x;
    int node = gid >> 5;
    int lane = gid & 31;
    if (node >= N_NODES) return;

    const float dv = g_dinv[node];
    const float4* h4 = (const float4*)hin;

    float4 acc = __ldg(&h4[node * 32 + lane]);

    int e0 = g_rowptr[node];
    int e1 = g_rowptr[node + 1];
    int e = e0;
    for (; e + 4 <= e1; e += 4) {
        int s0 = g_csrsrc[e], s1 = g_csrsrc[e + 1], s2 = g_csrsrc[e + 2], s3 = g_csrsrc[e + 3];
        float4 v0 = __ldg(&h4[s0 * 32 + lane]);
        float4 v1 = __ldg(&h4[s1 * 32 + lane]);
        float4 v2 = __ldg(&h4[s2 * 32 + lane]);
        float4 v3 = __ldg(&h4[s3 * 32 + lane]);
        acc.x += v0.x + v1.x + v2.x + v3.x;
        acc.y += v0.y + v1.y + v2.y + v3.y;
        acc.z += v0.z + v1.z + v2.z + v3.z;
        acc.w += v0.w + v1.w + v2.w + v3.w;
    }
    for (; e < e1; e++) {
        int s = g_csrsrc[e];
        float4 v = __ldg(&h4[s * 32 + lane]);
        acc.x += v.x; acc.y += v.y; acc.z += v.z; acc.w += v.w;
    }

    float4 b = ((const float4*)bias)[lane];
    int g = batch[node];
    float* p = &g_pool[g * 128 + lane * 4];
    atomicAdd(p + 0, fmaxf(acc.x * dv + b.x, 0.0f));
    atomicAdd(p + 1, fmaxf(acc.y * dv + b.y, 0.0f));
    atomicAdd(p + 2, fmaxf(acc.z * dv + b.z, 0.0f));
    atomicAdd(p + 3, fmaxf(acc.w * dv + b.w, 0.0f));
    if (lane == 0) atomicAdd(&g_pcnt[g], 1.0f);
}

// ---------------- final: out[512,64] = (pool/cnt) @ Wlin + blin; re-zero pool ----------------
__global__ void final_kernel(const float* __restrict__ Wlin,
                             const float* __restrict__ blin,
                             float* __restrict__ out) {
    __shared__ float ws[HID_CH * OUT_CH];
    __shared__ float bs[OUT_CH];
    for (int i = threadIdx.x; i < HID_CH * OUT_CH; i += 256) ws[i] = Wlin[i];
    if (threadIdx.x < OUT_CH) bs[threadIdx.x] = blin[threadIdx.x];
    __syncthreads();

    int t = blockIdx.x * 256 + threadIdx.x;    // block owns graphs [b*4, b*4+4)
    int g = t >> 6, o = t & 63;
    float inv = 1.0f / fmaxf(g_pcnt[g], 1.0f);
    float s = 0.0f;
#pragma unroll 8
    for (int k = 0; k < 128; k++)
        s += g_pool[g * 128 + k] * ws[k * 64 + o];
    out[t] = s * inv + bs[o];

    __syncthreads();   // all reads of this block's g_pool graphs done
    int base = blockIdx.x * 512;               // 4 graphs * 128 ch
    g_pool[base + threadIdx.x] = 0.0f;
    g_pool[base + 256 + threadIdx.x] = 0.0f;
    if (threadIdx.x < 4) g_pcnt[blockIdx.x * 4 + threadIdx.x] = 0.0f;
}

// ---------------- launch (fork-join: CSR build overlaps split_w + GEMM1) ----------------
extern "C" void kernel_launch(void* const* d_in, const int* in_sizes, int n_in,
                              void* d_out, int out_size) {
    const float* x    = (const float*)d_in[0];
    const float* W1   = (const float*)d_in[1];
    const float* b1   = (const float*)d_in[2];
    const float* W2   = (const float*)d_in[3];
    const float* b2   = (const float*)d_in[4];
    const float* Wlin = (const float*)d_in[5];
    const float* blin = (const float*)d_in[6];
    const int* edge   = (const int*)d_in[7];     // JAX x64-disabled: int64 -> int32
    const int* batch  = (const int*)d_in[8];
    float* out = (float*)d_out;

    const int* src = edge;
    const int* dst = edge + N_EDGES;

    float *t1, *t2, *dinv;
    __nv_bfloat16 *wh1, *wl1, *wh2, *wl2;
    cudaGetSymbolAddress((void**)&t1, g_t1);
    cudaGetSymbolAddress((void**)&t2, g_t2);
    cudaGetSymbolAddress((void**)&dinv, g_dinv);
    cudaGetSymbolAddress((void**)&wh1, g_wh1);
    cudaGetSymbolAddress((void**)&wl1, g_wl1);
    cudaGetSymbolAddress((void**)&wh2, g_wh2);
    cudaGetSymbolAddress((void**)&wl2, g_wl2);

    cudaFuncSetAttribute(gemm_tc, cudaFuncAttributeMaxDynamicSharedMemorySize, SMEM_TC);

    // host-side stream/event handles, created once (no device memory involved)
    static cudaStream_t s_side = nullptr;
    static cudaEvent_t ev_fork = nullptr, ev_join = nullptr;
    if (s_side == nullptr) {
        cudaStreamCreateWithFlags(&s_side, cudaStreamNonBlocking);
        cudaEventCreateWithFlags(&ev_fork, cudaEventDisableTiming);
        cudaEventCreateWithFlags(&ev_join, cudaEventDisableTiming);
    }

    const int eb = (N_EDGES + 255) / 256;               // 2344
    const int gb = (N_NODES + 63) / 64;                 // 782
    const int ab = (N_NODES * 32) / 256;                // 6250

    // fork: CSR build on side stream, fully concurrent with split_w + GEMM1
    cudaEventRecord(ev_fork, 0);
    cudaStreamWaitEvent(s_side, ev_fork, 0);
    hist_kernel<<<eb, 256, 0, s_side>>>(dst);
    scan_kernel<<<1, 1024, 0, s_side>>>();
    fill_kernel<<<eb, 256, 0, s_side>>>(src, dst);
    cudaEventRecord(ev_join, s_side);

    // main stream: GEMM1 has NO dinv dependency (unscaled output) -> real overlap
    split_w_both<<<128, 256>>>(W1, W2);
    gemm_tc<<<gb, 256, SMEM_TC>>>(x, wh1, wl1, nullptr, t1, N_NODES);

    // join: agg1 needs rowptr/csrsrc/dinv from the side stream
    cudaStreamWaitEvent(0, ev_join, 0);
    agg_scale_kernel<<<ab, 256>>>(t1, t2, b1);

    gemm_tc<<<gb, 256, SMEM_TC>>>(t2, wh2, wl2, dinv, t1, N_NODES);
    agg_pool_kernel<<<ab, 256>>>(t1, b2, batch);

    final_kernel<<<128, 256>>>(Wlin, blin, out);
}

// round 9
// speedup vs baseline: 1.3066x; 1.0225x over previous
#include <cuda_runtime.h>
#include <cuda_bf16.h>
#include <mma.h>
#include <cstdint>

using namespace nvcuda;

#define N_NODES 50000
#define N_EDGES 600000
#define IN_CH 128
#define HID_CH 128
#define OUT_CH 64
#define NUM_GRAPHS 512

// ---------------- device scratch (zero-initialized at load; every call leaves
// g_cnt / g_pool / g_pcnt zeroed again, so replays are identical) ----------------
__device__ float g_t1[N_NODES * HID_CH];       // 25.6 MB
__device__ float g_t2[N_NODES * HID_CH];       // 25.6 MB
__device__ int   g_cnt[N_NODES];
__device__ float g_dinv[N_NODES];
__device__ int   g_rowptr[N_NODES + 1];
__device__ int   g_cursor[N_NODES];
__device__ int   g_csrsrc[N_EDGES];
__device__ float g_pool[NUM_GRAPHS * HID_CH];
__device__ float g_pcnt[NUM_GRAPHS];
__device__ __nv_bfloat16 g_wh1[HID_CH * HID_CH];   // W1^T hi, [n][k]
__device__ __nv_bfloat16 g_wl1[HID_CH * HID_CH];   // W1^T lo
__device__ __nv_bfloat16 g_wh2[HID_CH * HID_CH];   // W2^T hi
__device__ __nv_bfloat16 g_wl2[HID_CH * HID_CH];   // W2^T lo

__device__ __forceinline__ void split_bf16(float x, unsigned short& h, unsigned short& l) {
    __nv_bfloat16 hb = __float2bfloat16_rn(x);
    float r = x - __bfloat162float(hb);
    __nv_bfloat16 lb = __float2bfloat16_rn(r);
    h = __bfloat16_as_ushort(hb);
    l = __bfloat16_as_ushort(lb);
}

// ---------------- histogram of in-degrees (real edges only) ----------------
__global__ void hist_kernel(const int* __restrict__ dst) {
    int i = blockIdx.x * blockDim.x + threadIdx.x;
    if (i < N_EDGES) atomicAdd(&g_cnt[dst[i]], 1);
}

// ---------------- single-block scan -> rowptr, cursor, dinv; re-zeroes g_cnt ----------------
__global__ void scan_kernel() {
    __shared__ int part[1024];
    const int tid = threadIdx.x;
    const int chunk = (N_NODES + 1023) / 1024;   // 49
    int start = tid * chunk;
    int end = start + chunk; if (end > N_NODES) end = N_NODES;
    int s = 0;
    for (int i = start; i < end; i++) s += g_cnt[i];
    part[tid] = s;
    __syncthreads();
    for (int off = 1; off < 1024; off <<= 1) {
        int v = 0;
        if (tid >= off) v = part[tid - off];
        __syncthreads();
        part[tid] += v;
        __syncthreads();
    }
    int run = (tid == 0) ? 0 : part[tid - 1];
    for (int i = start; i < end; i++) {
        int c = g_cnt[i];
        g_cnt[i] = 0;                           // ready for next call
        g_rowptr[i] = run;
        g_cursor[i] = run;
        g_dinv[i] = rsqrtf((float)(c + 1));     // +1 self-loop
        run += c;
    }
    if (tid == 1023) g_rowptr[N_NODES] = part[1023];
}

// ---------------- fill CSR (src indices grouped by dst) ----------------
__global__ void fill_kernel(const int* __restrict__ src,
                            const int* __restrict__ dst) {
    int i = blockIdx.x * blockDim.x + threadIdx.x;
    if (i < N_EDGES) {
        int d = dst[i];
        int pos = atomicAdd(&g_cursor[d], 1);
        g_csrsrc[pos] = src[i];
    }
}

// ---------------- W split+transpose for BOTH layers in one launch ----------------
__global__ void split_w_both(const float* __restrict__ W1,
                             const float* __restrict__ W2) {
    int i = blockIdx.x * blockDim.x + threadIdx.x;   // 32768
    unsigned short h, l;
    if (i < 16384) {
        int k = i >> 7, n = i & 127;
        split_bf16(W1[i], h, l);
        g_wh1[n * 128 + k] = __ushort_as_bfloat16(h);
        g_wl1[n * 128 + k] = __ushort_as_bfloat16(l);
    } else {
        int j = i - 16384;
        int k = j >> 7, n = j & 127;
        split_bf16(W2[j], h, l);
        g_wh2[n * 128 + k] = __ushort_as_bfloat16(h);
        g_wl2[n * 128 + k] = __ushort_as_bfloat16(l);
    }
}

// ============ tensor-core GEMM via wmma: C = A @ W (unscaled) ============
// 64x128 output tile per CTA, 256 threads = 8 warps in a 2(M)x4(N) grid, 32x32/warp.
// bf16 hi/lo split, 3 passes (Ah*Bh + Ah*Bl + Al*Bh), fp32 accumulators.
// Full tiles store accumulators DIRECTLY to global; ragged tail stages via smem.
#define KP 136                                  // padded K stride in bf16 elements
// smem: Ah(64*KP) Al(64*KP) Bh(128*KP) Bl(128*KP) bf16 = 104448 B -> 2 CTAs/SM
#define SMEM_TC ((64 + 64 + 128 + 128) * KP * 2)

__global__ __launch_bounds__(256, 2)
void gemm_tc(const float* __restrict__ A,
             const __nv_bfloat16* __restrict__ wh,
             const __nv_bfloat16* __restrict__ wl,
             float* __restrict__ C, int M) {
    extern __shared__ char smc[];
    __nv_bfloat16* Ah = (__nv_bfloat16*)smc;
    __nv_bfloat16* Al = Ah + 64 * KP;
    __nv_bfloat16* Bh = Al + 64 * KP;
    __nv_bfloat16* Bl = Bh + 128 * KP;

    const int tid = threadIdx.x;
    const int row0 = blockIdx.x * 64;

    // ---- stage A (hi/lo split), [r][k] row-major, padded ----
    const float4* A4 = (const float4*)A;
    for (int idx = tid; idx < 64 * 32; idx += 256) {
        int r = idx >> 5;
        int kq = idx & 31;                       // float4 index along k
        int row = row0 + r;
        float4 v = make_float4(0.f, 0.f, 0.f, 0.f);
        if (row < M) v = A4[row * 32 + kq];
        unsigned short h0, h1, h2, h3, l0, l1, l2, l3;
        split_bf16(v.x, h0, l0); split_bf16(v.y, h1, l1);
        split_bf16(v.z, h2, l2); split_bf16(v.w, h3, l3);
        int e = r * KP + kq * 4;                 // 8B-aligned element offset
        *(uint2*)&Ah[e] = make_uint2((uint32_t)h0 | ((uint32_t)h1 << 16),
                                     (uint32_t)h2 | ((uint32_t)h3 << 16));
        *(uint2*)&Al[e] = make_uint2((uint32_t)l0 | ((uint32_t)l1 << 16),
                                     (uint32_t)l2 | ((uint32_t)l3 << 16));
    }

    // ---- stage B: plain copy of pre-split W^T [n][k] bf16 ----
    {
        const uint4* whg = (const uint4*)wh;     // 2048 uint4 (8 bf16 each)
        const uint4* wlg = (const uint4*)wl;
        for (int idx = tid; idx < 2048; idx += 256) {
            int n = idx >> 4, q = idx & 15;
            *(uint4*)&Bh[n * KP + q * 8] = whg[idx];
            *(uint4*)&Bl[n * KP + q * 8] = wlg[idx];
        }
    }
    __syncthreads();

    // ---- wmma main loops: warp (wm, wn) owns rows wm*32..+32, cols wn*32..+32 ----
    const int wid = tid >> 5;
    const int wm = wid & 1;
    const int wn = wid >> 1;

    wmma::fragment<wmma::accumulator, 16, 16, 16, float> cf[2][2];
#pragma unroll
    for (int i = 0; i < 2; i++)
#pragma unroll
        for (int j = 0; j < 2; j++) wmma::fill_fragment(cf[i][j], 0.0f);

#pragma unroll
    for (int p = 0; p < 3; p++) {
        const __nv_bfloat16* Ap = (p == 2) ? Al : Ah;
        const __nv_bfloat16* Bp = (p == 1) ? Bl : Bh;
#pragma unroll
        for (int k8 = 0; k8 < 8; k8++) {
            wmma::fragment<wmma::matrix_a, 16, 16, 16, __nv_bfloat16, wmma::row_major> a0, a1;
            wmma::load_matrix_sync(a0, Ap + (wm * 32 + 0)  * KP + k8 * 16, KP);
            wmma::load_matrix_sync(a1, Ap + (wm * 32 + 16) * KP + k8 * 16, KP);
            wmma::fragment<wmma::matrix_b, 16, 16, 16, __nv_bfloat16, wmma::col_major> b0, b1;
            wmma::load_matrix_sync(b0, Bp + (wn * 32 + 0)  * KP + k8 * 16, KP);
            wmma::load_matrix_sync(b1, Bp + (wn * 32 + 16) * KP + k8 * 16, KP);
            wmma::mma_sync(cf[0][0], a0, b0, cf[0][0]);
            wmma::mma_sync(cf[0][1], a0, b1, cf[0][1]);
            wmma::mma_sync(cf[1][0], a1, b0, cf[1][0]);
            wmma::mma_sync(cf[1][1], a1, b1, cf[1][1]);
        }
    }

    if (row0 + 64 <= M) {
        // full tile: accumulators straight to global
#pragma unroll
        for (int i = 0; i < 2; i++)
#pragma unroll
            for (int j = 0; j < 2; j++)
                wmma::store_matrix_sync(&C[(row0 + wm * 32 + i * 16) * 128 + wn * 32 + j * 16],
                                        cf[i][j], 128, wmma::mem_row_major);
    } else {
        // ragged tail block: stage via smem, guarded writes
        __syncthreads();
        float* cs = (float*)smc;                 // 64x128 f32 = 32KB
#pragma unroll
        for (int i = 0; i < 2; i++)
#pragma unroll
            for (int j = 0; j < 2; j++)
                wmma::store_matrix_sync(&cs[(wm * 32 + i * 16) * 128 + wn * 32 + j * 16],
                                        cf[i][j], 128, wmma::mem_row_major);
        __syncthreads();
        float4* C4 = (float4*)C;
        const float4* cs4 = (const float4*)cs;
        for (int idx = tid; idx < 64 * 32; idx += 256) {
            int r = idx >> 5, cq = idx & 31;
            int row = row0 + r;
            if (row < M) C4[row * 32 + cq] = cs4[r * 32 + cq];
        }
    }
}

// ------------- aggregation on UNSCALED h (applies dinv[s] per edge), 8x unroll -------------
// out[d] = relu(dinv[d] * (sum_s h[s]*dinv[s] + h[d]*dinv[d]) + b)
__global__ void agg_scale_kernel(const float* __restrict__ hin,
                                 float* __restrict__ hout,
                                 const float* __restrict__ bias) {
    int gid = blockIdx.x * blockDim.x + threadIdx.x;
    int node = gid >> 5;
    int lane = gid & 31;
    if (node >= N_NODES) return;

    const float dv = g_dinv[node];
    const float4* h4 = (const float4*)hin;

    float4 acc = __ldg(&h4[node * 32 + lane]);   // self-loop (unscaled)
    acc.x *= dv; acc.y *= dv; acc.z *= dv; acc.w *= dv;

    int e0 = g_rowptr[node];
    int e1 = g_rowptr[node + 1];
    int e = e0;
    for (; e + 8 <= e1; e += 8) {
        int si[8]; float ci[8]; float4 vi[8];
#pragma unroll
        for (int q = 0; q < 8; q++) si[q] = g_csrsrc[e + q];
#pragma unroll
        for (int q = 0; q < 8; q++) ci[q] = g_dinv[si[q]];
#pragma unroll
        for (int q = 0; q < 8; q++) vi[q] = __ldg(&h4[si[q] * 32 + lane]);
#pragma unroll
        for (int q = 0; q < 8; q++) {
            acc.x += vi[q].x * ci[q];
            acc.y += vi[q].y * ci[q];
            acc.z += vi[q].z * ci[q];
            acc.w += vi[q].w * ci[q];
        }
    }
    for (; e + 4 <= e1; e += 4) {
        int s0 = g_csrsrc[e], s1 = g_csrsrc[e + 1], s2 = g_csrsrc[e + 2], s3 = g_csrsrc[e + 3];
        float c0 = g_dinv[s0], c1 = g_dinv[s1], c2 = g_dinv[s2], c3 = g_dinv[s3];
        float4 v0 = __ldg(&h4[s0 * 32 + lane]);
        float4 v1 = __ldg(&h4[s1 * 32 + lane]);
        float4 v2 = __ldg(&h4[s2 * 32 + lane]);
        float4 v3 = __ldg(&h4[s3 * 32 + lane]);
        acc.x += v0.x * c0 + v1.x * c1 + v2.x * c2 + v3.x * c3;
        acc.y += v0.y * c0 + v1.y * c1 + v2.y * c2 + v3.y * c3;
        acc.z += v0.z * c0 + v1.z * c1 + v2.z * c2 + v3.z * c3;
        acc.w += v0.w * c0 + v1.w * c1 + v2.w * c2 + v3.w * c3;
    }
    for (; e < e1; e++) {
        int s = g_csrsrc[e];
        float c = g_dinv[s];
        float4 v = __ldg(&h4[s * 32 + lane]);
        acc.x += v.x * c; acc.y += v.y * c; acc.z += v.z * c; acc.w += v.w * c;
    }

    float4 b = ((const float4*)bias)[lane];
    acc.x = fmaxf(acc.x * dv + b.x, 0.0f);
    acc.y = fmaxf(acc.y * dv + b.y, 0.0f);
    acc.z = fmaxf(acc.z * dv + b.z, 0.0f);
    acc.w = fmaxf(acc.w * dv + b.w, 0.0f);
    ((float4*)hout)[node * 32 + lane] = acc;
}

// ------- layer-2: same scaled aggregation, fused with mean-pool accumulation -------
__global__ void agg_scale_pool_kernel(const float* __restrict__ hin,
                                      const float* __restrict__ bias,
                                      const int* __restrict__ batch) {
    int gid = blockIdx.x * blockDim.x + threadIdx.x;
    int node = gid >> 5;
    int lane = gid & 31;
    if (node >= N_NODES) return;

    const float dv = g_dinv[node];
    const float4* h4 = (const float4*)hin;

    float4 acc = __ldg(&h4[node * 32 + lane]);
    acc.x *= dv; acc.y *= dv; acc.z *= dv; acc.w *= dv;

    int e0 = g_rowptr[node];
    int e1 = g_rowptr[node + 1];
    int e = e0;
    for (; e + 8 <= e1; e += 8) {
        int si[8]; float ci[8]; float4 vi[8];
#pragma unroll
        for (int q = 0; q < 8; q++) si[q] = g_csrsrc[e + q];
#pragma unroll
        for (int q = 0; q < 8; q++) ci[q] = g_dinv[si[q]];
#pragma unroll
        for (int q = 0; q < 8; q++) vi[q] = __ldg(&h4[si[q] * 32 + lane]);
#pragma unroll
        for (int q = 0; q < 8; q++) {
            acc.x += vi[q].x * ci[q];
            acc.y += vi[q].y * ci[q];
            acc.z += vi[q].z * ci[q];
            acc.w += vi[q].w * ci[q];
        }
    }
    for (; e + 4 <= e1; e += 4) {
        int s0 = g_csrsrc[e], s1 = g_csrsrc[e + 1], s2 = g_csrsrc[e + 2], s3 = g_csrsrc[e + 3];
        float c0 = g_dinv[s0], c1 = g_dinv[s1], c2 = g_dinv[s2], c3 = g_dinv[s3];
        float4 v0 = __ldg(&h4[s0 * 32 + lane]);
        float4 v1 = __ldg(&h4[s1 * 32 + lane]);
        float4 v2 = __ldg(&h4[s2 * 32 + lane]);
        float4 v3 = __ldg(&h4[s3 * 32 + lane]);
        acc.x += v0.x * c0 + v1.x * c1 + v2.x * c2 + v3.x * c3;
        acc.y += v0.y * c0 + v1.y * c1 + v2.y * c2 + v3.y * c3;
        acc.z += v0.z * c0 + v1.z * c1 + v2.z * c2 + v3.z * c3;
        acc.w += v0.w * c0 + v1.w * c1 + v2.w * c2 + v3.w * c3;
    }
    for (; e < e1; e++) {
        int s = g_csrsrc[e];
        float c = g_dinv[s];
        float4 v = __ldg(&h4[s * 32 + lane]);
        acc.x += v.x * c; acc.y += v.y * c; acc.z += v.z * c; acc.w += v.w * c;
    }

    float4 b = ((const float4*)bias)[lane];
    int g = batch[node];
    float* p = &g_pool[g * 128 + lane * 4];
    atomicAdd(p + 0, fmaxf(acc.x * dv + b.x, 0.0f));
    atomicAdd(p + 1, fmaxf(acc.y * dv + b.y, 0.0f));
    atomicAdd(p + 2, fmaxf(acc.z * dv + b.z, 0.0f));
    atomicAdd(p + 3, fmaxf(acc.w * dv + b.w, 0.0f));
    if (lane == 0) atomicAdd(&g_pcnt[g], 1.0f);
}

// ---------------- final: out[512,64] = (pool/cnt) @ Wlin + blin; re-zero pool ----------------
__global__ void final_kernel(const float* __restrict__ Wlin,
                             const float* __restrict__ blin,
                             float* __restrict__ out) {
    __shared__ float ws[HID_CH * OUT_CH];
    __shared__ float bs[OUT_CH];
    for (int i = threadIdx.x; i < HID_CH * OUT_CH; i += 256) ws[i] = Wlin[i];
    if (threadIdx.x < OUT_CH) bs[threadIdx.x] = blin[threadIdx.x];
    __syncthreads();

    int t = blockIdx.x * 256 + threadIdx.x;    // block owns graphs [b*4, b*4+4)
    int g = t >> 6, o = t & 63;
    float inv = 1.0f / fmaxf(g_pcnt[g], 1.0f);
    float s = 0.0f;
#pragma unroll 8
    for (int k = 0; k < 128; k++)
        s += g_pool[g * 128 + k] * ws[k * 64 + o];
    out[t] = s * inv + bs[o];

    __syncthreads();   // all reads of this block's g_pool graphs done
    int base = blockIdx.x * 512;               // 4 graphs * 128 ch
    g_pool[base + threadIdx.x] = 0.0f;
    g_pool[base + 256 + threadIdx.x] = 0.0f;
    if (threadIdx.x < 4) g_pcnt[blockIdx.x * 4 + threadIdx.x] = 0.0f;
}

// ---------------- launch (fork-join: CSR build overlaps split_w + GEMM1) ----------------
extern "C" void kernel_launch(void* const* d_in, const int* in_sizes, int n_in,
                              void* d_out, int out_size) {
    const float* x    = (const float*)d_in[0];
    const float* W1   = (const float*)d_in[1];
    const float* b1   = (const float*)d_in[2];
    const float* W2   = (const float*)d_in[3];
    const float* b2   = (const float*)d_in[4];
    const float* Wlin = (const float*)d_in[5];
    const float* blin = (const float*)d_in[6];
    const int* edge   = (const int*)d_in[7];     // JAX x64-disabled: int64 -> int32
    const int* batch  = (const int*)d_in[8];
    float* out = (float*)d_out;

    const int* src = edge;
    const int* dst = edge + N_EDGES;

    float *t1, *t2;
    __nv_bfloat16 *wh1, *wl1, *wh2, *wl2;
    cudaGetSymbolAddress((void**)&t1, g_t1);
    cudaGetSymbolAddress((void**)&t2, g_t2);
    cudaGetSymbolAddress((void**)&wh1, g_wh1);
    cudaGetSymbolAddress((void**)&wl1, g_wl1);
    cudaGetSymbolAddress((void**)&wh2, g_wh2);
    cudaGetSymbolAddress((void**)&wl2, g_wl2);

    cudaFuncSetAttribute(gemm_tc, cudaFuncAttributeMaxDynamicSharedMemorySize, SMEM_TC);

    // host-side stream/event handles, created once (no device memory involved)
    static cudaStream_t s_side = nullptr;
    static cudaEvent_t ev_fork = nullptr, ev_join = nullptr;
    if (s_side == nullptr) {
        cudaStreamCreateWithFlags(&s_side, cudaStreamNonBlocking);
        cudaEventCreateWithFlags(&ev_fork, cudaEventDisableTiming);
        cudaEventCreateWithFlags(&ev_join, cudaEventDisableTiming);
    }

    const int eb = (N_EDGES + 255) / 256;               // 2344
    const int gb = (N_NODES + 63) / 64;                 // 782
    const int ab = (N_NODES * 32) / 256;                // 6250

    // fork: CSR build on side stream, fully concurrent with split_w + GEMM1
    cudaEventRecord(ev_fork, 0);
    cudaStreamWaitEvent(s_side, ev_fork, 0);
    hist_kernel<<<eb, 256, 0, s_side>>>(dst);
    scan_kernel<<<1, 1024, 0, s_side>>>();
    fill_kernel<<<eb, 256, 0, s_side>>>(src, dst);
    cudaEventRecord(ev_join, s_side);

    // main stream: GEMM1 has no CSR/dinv dependency -> real overlap
    split_w_both<<<128, 256>>>(W1, W2);
    gemm_tc<<<gb, 256, SMEM_TC>>>(x, wh1, wl1, t1, N_NODES);

    // join: agg1 needs rowptr/csrsrc/dinv from the side stream
    cudaStreamWaitEvent(0, ev_join, 0);
    agg_scale_kernel<<<ab, 256>>>(t1, t2, b1);

    gemm_tc<<<gb, 256, SMEM_TC>>>(t2, wh2, wl2, t1, N_NODES);
    agg_scale_pool_kernel<<<ab, 256>>>(t1, b2, batch);

    final_kernel<<<128, 256>>>(Wlin, blin, out);
}